// round 5
// baseline (speedup 1.0000x reference)
#include <cuda_runtime.h>
#include <cuda_bf16.h>
#include <cstddef>

// Problem constants
#define S_LEN  2048
#define NB     2
#define NH     16
#define NKV    4
#define DH     128
#define DMODEL 2048   // NH*DH
#define KVD    512    // NKV*DH
#define NTOK   (NB*S_LEN)   // 4096

// Scratch (device globals — no allocations allowed)
__device__ float g_q[(size_t)NTOK * DMODEL];
__device__ float g_k[(size_t)NTOK * KVD];
__device__ float g_v[(size_t)NTOK * KVD];
__device__ float g_o[(size_t)NTOK * DMODEL];

// ---------------------------------------------------------------------------
// Tiled SGEMM: C[M,N] = A[M,K] @ B[K,N] (+ R[M,N] if R != nullptr)
// BM=BN=128, BK=16, 256 threads, 8x8 per-thread micro-tile.
// Requires M%128==0, N%128==0, K%16==0 (true for all our shapes).
// ---------------------------------------------------------------------------
__global__ __launch_bounds__(256) void sgemm128(
    const float* __restrict__ A, const float* __restrict__ B,
    float* __restrict__ C, const float* __restrict__ R,
    int M, int N, int K)
{
    __shared__ float As[16][128];   // A tile transposed: As[k][m]
    __shared__ float Bs[16][128];   // Bs[k][n]

    const int tid = threadIdx.x;
    const int tm  = tid >> 4;       // 0..15
    const int tn  = tid & 15;       // 0..15
    const int row0 = blockIdx.y * 128;
    const int col0 = blockIdx.x * 128;

    float acc[8][8];
#pragma unroll
    for (int i = 0; i < 8; i++)
#pragma unroll
        for (int j = 0; j < 8; j++) acc[i][j] = 0.f;

    for (int kt = 0; kt < K; kt += 16) {
#pragma unroll
        for (int i = 0; i < 2; i++) {
            int idx = tid + i * 256;          // 0..511
            // A tile: 128 rows x 16 cols = 512 float4 (4 f4 per row)
            int ar = idx >> 2;                // 0..127
            int ac = (idx & 3) << 2;          // 0,4,8,12
            float4 a = *(const float4*)&A[(size_t)(row0 + ar) * K + kt + ac];
            As[ac + 0][ar] = a.x;
            As[ac + 1][ar] = a.y;
            As[ac + 2][ar] = a.z;
            As[ac + 3][ar] = a.w;
            // B tile: 16 rows x 128 cols = 512 float4 (32 f4 per row)
            int br = idx >> 5;                // 0..15
            int bc = (idx & 31) << 2;         // 0..124
            *(float4*)&Bs[br][bc] =
                *(const float4*)&B[(size_t)(kt + br) * N + col0 + bc];
        }
        __syncthreads();

#pragma unroll
        for (int k = 0; k < 16; k++) {
            float4 a0 = *(float4*)&As[k][tm * 8];
            float4 a1 = *(float4*)&As[k][tm * 8 + 4];
            float4 b0 = *(float4*)&Bs[k][tn * 8];
            float4 b1 = *(float4*)&Bs[k][tn * 8 + 4];
            float ra[8] = {a0.x, a0.y, a0.z, a0.w, a1.x, a1.y, a1.z, a1.w};
            float rb[8] = {b0.x, b0.y, b0.z, b0.w, b1.x, b1.y, b1.z, b1.w};
#pragma unroll
            for (int i = 0; i < 8; i++)
#pragma unroll
                for (int j = 0; j < 8; j++)
                    acc[i][j] = fmaf(ra[i], rb[j], acc[i][j]);
        }
        __syncthreads();
    }

#pragma unroll
    for (int i = 0; i < 8; i++) {
        size_t r = (size_t)(row0 + tm * 8 + i) * N;
#pragma unroll
        for (int j4 = 0; j4 < 8; j4 += 4) {
            int c = col0 + tn * 8 + j4;
            float4 v;
            v.x = acc[i][j4 + 0];
            v.y = acc[i][j4 + 1];
            v.z = acc[i][j4 + 2];
            v.w = acc[i][j4 + 3];
            if (R) {
                float4 rr = *(const float4*)&R[r + c];
                v.x += rr.x; v.y += rr.y; v.z += rr.z; v.w += rr.w;
            }
            *(float4*)&C[r + c] = v;
        }
    }
}

// ---------------------------------------------------------------------------
// Per-head RMSNorm over DH=128, in-place. One warp per head-row.
// ---------------------------------------------------------------------------
__global__ __launch_bounds__(256) void rmsnorm_heads(
    float* __restrict__ t, const float* __restrict__ gamma, int nrows)
{
    int row  = blockIdx.x * 8 + (threadIdx.x >> 5);
    if (row >= nrows) return;
    int lane = threadIdx.x & 31;

    float4 v = *(float4*)&t[(size_t)row * DH + lane * 4];
    float ss = v.x * v.x + v.y * v.y + v.z * v.z + v.w * v.w;
#pragma unroll
    for (int m = 16; m; m >>= 1) ss += __shfl_xor_sync(0xffffffffu, ss, m);
    float r = rsqrtf(ss * (1.0f / DH) + 1e-8f);

    float4 g = *(const float4*)&gamma[lane * 4];
    v.x *= r * g.x; v.y *= r * g.y; v.z *= r * g.z; v.w *= r * g.w;
    *(float4*)&t[(size_t)row * DH + lane * 4] = v;
}

// ---------------------------------------------------------------------------
// Flash-style causal attention, fp32.
// BQ=64 query rows per CTA, BK=64 key rows per tile, DH=128.
// 256 threads = 16x16; score stage: 4x4 per thread; PV stage: 4 rows x 8 cols.
// K and V share one smem buffer (loaded sequentially) -> 80KB smem, 2 CTA/SM.
// Grid: (S/64, NH, NB).
// ---------------------------------------------------------------------------
#define BQ 64
#define BKT 64

__global__ __launch_bounds__(256) void flash_attn(
    const float* __restrict__ Q, const float* __restrict__ K,
    const float* __restrict__ V, float* __restrict__ O)
{
    extern __shared__ float sm[];
    float* Qs  = sm;                 // 64*128
    float* KVs = Qs + BQ * DH;       // 64*128 (K then reused for V)
    float* Ps  = KVs + BKT * DH;     // 64*64

    const int bq = blockIdx.x;
    const int h  = blockIdx.y;
    const int b  = blockIdx.z;
    const int kvh = h >> 2;          // NH/NKV = 4

    const int tid = threadIdx.x;
    const int ty  = tid >> 4;        // 0..15 -> 4 query rows
    const int tx  = tid & 15;        // 0..15

    const float* Qg = Q + ((size_t)b * S_LEN * NH  + h)   * DH;  // row stride DMODEL
    const float* Kg = K + ((size_t)b * S_LEN * NKV + kvh) * DH;  // row stride KVD
    const float* Vg = V + ((size_t)b * S_LEN * NKV + kvh) * DH;
    float*       Og = O + ((size_t)b * S_LEN * NH  + h)   * DH;

    const float qscale = 0.08838834764831845f;  // 1/sqrt(DH)

    // Load Q tile (scaled)
    for (int i = tid; i < BQ * (DH / 4); i += 256) {
        int r  = i >> 5;
        int c4 = (i & 31) << 2;
        float4 v = *(const float4*)&Qg[(size_t)(bq * BQ + r) * DMODEL + c4];
        v.x *= qscale; v.y *= qscale; v.z *= qscale; v.w *= qscale;
        *(float4*)&Qs[r * DH + c4] = v;
    }

    float m[4], l[4];
    float acc[4][8];
#pragma unroll
    for (int r = 0; r < 4; r++) {
        m[r] = -1e30f; l[r] = 0.f;
#pragma unroll
        for (int j = 0; j < 8; j++) acc[r][j] = 0.f;
    }

    for (int t = 0; t <= bq; t++) {
        __syncthreads();   // protect KVs (read as V last iter) & Ps
        // Load K tile
        for (int i = tid; i < BKT * (DH / 4); i += 256) {
            int r  = i >> 5;
            int c4 = (i & 31) << 2;
            *(float4*)&KVs[r * DH + c4] =
                *(const float4*)&Kg[(size_t)(t * BKT + r) * KVD + c4];
        }
        __syncthreads();

        // Scores S = Q K^T  (4x4 per thread)
        float s[4][4];
#pragma unroll
        for (int r = 0; r < 4; r++)
#pragma unroll
            for (int c = 0; c < 4; c++) s[r][c] = 0.f;

        for (int k = 0; k < DH; k += 4) {
            float4 qa[4], kb[4];
#pragma unroll
            for (int r = 0; r < 4; r++)
                qa[r] = *(float4*)&Qs[(ty * 4 + r) * DH + k];
#pragma unroll
            for (int c = 0; c < 4; c++)
                kb[c] = *(float4*)&KVs[(tx * 4 + c) * DH + k];
#pragma unroll
            for (int r = 0; r < 4; r++)
#pragma unroll
                for (int c = 0; c < 4; c++) {
                    s[r][c] = fmaf(qa[r].x, kb[c].x, s[r][c]);
                    s[r][c] = fmaf(qa[r].y, kb[c].y, s[r][c]);
                    s[r][c] = fmaf(qa[r].z, kb[c].z, s[r][c]);
                    s[r][c] = fmaf(qa[r].w, kb[c].w, s[r][c]);
                }
        }

        // Causal mask on the diagonal tile
        if (t == bq) {
#pragma unroll
            for (int r = 0; r < 4; r++)
#pragma unroll
                for (int c = 0; c < 4; c++)
                    if (tx * 4 + c > ty * 4 + r) s[r][c] = -1e30f;
        }

        // Online softmax update + write P
#pragma unroll
        for (int r = 0; r < 4; r++) {
            float mx = fmaxf(fmaxf(s[r][0], s[r][1]), fmaxf(s[r][2], s[r][3]));
#pragma unroll
            for (int d = 1; d < 16; d <<= 1)
                mx = fmaxf(mx, __shfl_xor_sync(0xffffffffu, mx, d));
            float mn = fmaxf(m[r], mx);
            float sc = __expf(m[r] - mn);
            m[r] = mn;
            float rs = 0.f;
#pragma unroll
            for (int c = 0; c < 4; c++) {
                float p = __expf(s[r][c] - mn);
                s[r][c] = p;
                rs += p;
            }
#pragma unroll
            for (int d = 1; d < 16; d <<= 1)
                rs += __shfl_xor_sync(0xffffffffu, rs, d);
            l[r] = l[r] * sc + rs;
#pragma unroll
            for (int j = 0; j < 8; j++) acc[r][j] *= sc;
#pragma unroll
            for (int c = 0; c < 4; c++)
                Ps[(ty * 4 + r) * BKT + tx * 4 + c] = s[r][c];
        }
        __syncthreads();   // Ks reads done, Ps visible

        // Load V tile into the same buffer
        for (int i = tid; i < BKT * (DH / 4); i += 256) {
            int r  = i >> 5;
            int c4 = (i & 31) << 2;
            *(float4*)&KVs[r * DH + c4] =
                *(const float4*)&Vg[(size_t)(t * BKT + r) * KVD + c4];
        }
        __syncthreads();

        // PV: acc[r][0..7] over cols tx*8..tx*8+7
        for (int k = 0; k < BKT; k++) {
            float p0 = Ps[(ty * 4 + 0) * BKT + k];
            float p1 = Ps[(ty * 4 + 1) * BKT + k];
            float p2 = Ps[(ty * 4 + 2) * BKT + k];
            float p3 = Ps[(ty * 4 + 3) * BKT + k];
            float4 v0 = *(float4*)&KVs[k * DH + tx * 8];
            float4 v1 = *(float4*)&KVs[k * DH + tx * 8 + 4];
            float pv[4] = {p0, p1, p2, p3};
#pragma unroll
            for (int r = 0; r < 4; r++) {
                acc[r][0] = fmaf(pv[r], v0.x, acc[r][0]);
                acc[r][1] = fmaf(pv[r], v0.y, acc[r][1]);
                acc[r][2] = fmaf(pv[r], v0.z, acc[r][2]);
                acc[r][3] = fmaf(pv[r], v0.w, acc[r][3]);
                acc[r][4] = fmaf(pv[r], v1.x, acc[r][4]);
                acc[r][5] = fmaf(pv[r], v1.y, acc[r][5]);
                acc[r][6] = fmaf(pv[r], v1.z, acc[r][6]);
                acc[r][7] = fmaf(pv[r], v1.w, acc[r][7]);
            }
        }
    }

    // Normalize + write
#pragma unroll
    for (int r = 0; r < 4; r++) {
        float inv = 1.f / l[r];
        float4 o0, o1;
        o0.x = acc[r][0] * inv; o0.y = acc[r][1] * inv;
        o0.z = acc[r][2] * inv; o0.w = acc[r][3] * inv;
        o1.x = acc[r][4] * inv; o1.y = acc[r][5] * inv;
        o1.z = acc[r][6] * inv; o1.w = acc[r][7] * inv;
        size_t orow = (size_t)(bq * BQ + ty * 4 + r) * DMODEL + tx * 8;
        *(float4*)&Og[orow]     = o0;
        *(float4*)&Og[orow + 4] = o1;
    }
}

// ---------------------------------------------------------------------------
extern "C" void kernel_launch(void* const* d_in, const int* in_sizes, int n_in,
                              void* d_out, int out_size)
{
    const float* x  = (const float*)d_in[0];
    const float* Wq = (const float*)d_in[1];
    const float* Wk = (const float*)d_in[2];
    const float* Wv = (const float*)d_in[3];
    const float* Wo = (const float*)d_in[4];
    const float* qg = (const float*)d_in[5];
    const float* kg = (const float*)d_in[6];
    float* out = (float*)d_out;

    float *pq, *pk, *pv, *po;
    cudaGetSymbolAddress((void**)&pq, g_q);
    cudaGetSymbolAddress((void**)&pk, g_k);
    cudaGetSymbolAddress((void**)&pv, g_v);
    cudaGetSymbolAddress((void**)&po, g_o);

    // QKV projections
    sgemm128<<<dim3(DMODEL / 128, NTOK / 128), 256>>>(x, Wq, pq, nullptr, NTOK, DMODEL, DMODEL);
    sgemm128<<<dim3(KVD    / 128, NTOK / 128), 256>>>(x, Wk, pk, nullptr, NTOK, KVD,    DMODEL);
    sgemm128<<<dim3(KVD    / 128, NTOK / 128), 256>>>(x, Wv, pv, nullptr, NTOK, KVD,    DMODEL);

    // Per-head RMSNorm (in place)
    rmsnorm_heads<<<(NTOK * NH  + 7) / 8, 256>>>(pq, qg, NTOK * NH);
    rmsnorm_heads<<<(NTOK * NKV + 7) / 8, 256>>>(pk, kg, NTOK * NKV);

    // Causal GQA attention
    int smem = (BQ * DH + BKT * DH + BQ * BKT) * sizeof(float);  // 80 KB
    cudaFuncSetAttribute(flash_attn, cudaFuncAttributeMaxDynamicSharedMemorySize, smem);
    flash_attn<<<dim3(S_LEN / BQ, NH, NB), 256, smem>>>(pq, pk, pv, po);

    // Output projection + residual
    sgemm128<<<dim3(DMODEL / 128, NTOK / 128), 256>>>(po, Wo, out, x, NTOK, DMODEL, DMODEL);
}

// round 6
// speedup vs baseline: 1.4044x; 1.4044x over previous
#include <cuda_runtime.h>
#include <cuda_bf16.h>
#include <cstdint>
#include <cstddef>

// Problem constants
#define S_LEN  2048
#define NB     2
#define NH     16
#define NKV    4
#define DH     128
#define DMODEL 2048   // NH*DH
#define KVD    512    // NKV*DH
#define NTOK   (NB*S_LEN)   // 4096

// Scratch (device globals — no allocations allowed)
__device__ float g_q[(size_t)NTOK * DMODEL];
__device__ float g_k[(size_t)NTOK * KVD];
__device__ float g_v[(size_t)NTOK * KVD];
__device__ float g_o[(size_t)NTOK * DMODEL];

// ---------------------------------------------------------------------------
// TF32 tensor-core GEMM: C[M,N] = A[M,K] @ B[K,N] (+ R if R != nullptr)
// BM=BN=128, BK=32, 256 threads (8 warps), warp tile 64x32 via m16n8k8 tf32.
// Double-buffered smem fed by cp.async. fp32 accumulate.
// Requires M%128==0, N%128==0, K%32==0.
// ---------------------------------------------------------------------------
#define AS_STRIDE 36           // floats per A row  (bank: 4r+c permutation)
#define BS_STRIDE 136          // floats per B row  (bank: 8c+r permutation)
#define ASZ (128 * AS_STRIDE)  // 4608 floats
#define BSZ (32  * BS_STRIDE)  // 4352 floats
#define GEMM_SMEM ((2 * (ASZ + BSZ)) * (int)sizeof(float))  // 71680 B

__device__ __forceinline__ uint32_t f2tf32(float x) {
    uint32_t y;
    asm("cvt.rna.tf32.f32 %0, %1;" : "=r"(y) : "f"(x));
    return y;
}

#define MMA_TF32(d, a, b)                                               \
    asm volatile(                                                       \
        "mma.sync.aligned.m16n8k8.row.col.f32.tf32.tf32.f32 "           \
        "{%0,%1,%2,%3}, {%4,%5,%6,%7}, {%8,%9}, {%0,%1,%2,%3};\n"       \
        : "+f"(d[0]), "+f"(d[1]), "+f"(d[2]), "+f"(d[3])                \
        : "r"(a[0]), "r"(a[1]), "r"(a[2]), "r"(a[3]),                   \
          "r"(b[0]), "r"(b[1]))

__global__ __launch_bounds__(256, 2) void tf32gemm(
    const float* __restrict__ A, const float* __restrict__ B,
    float* __restrict__ C, const float* __restrict__ R,
    int M, int N, int K)
{
    extern __shared__ float sm[];
    float* Asm = sm;                 // 2 buffers of ASZ
    float* Bsm = sm + 2 * ASZ;       // 2 buffers of BSZ

    const int tid  = threadIdx.x;
    const int wid  = tid >> 5;
    const int lane = tid & 31;
    const int wm   = wid >> 2;       // 0..1 -> row offset wm*64
    const int wn   = wid & 3;        // 0..3 -> col offset wn*32
    const int r    = lane >> 2;      // 0..7
    const int cq   = lane & 3;       // 0..3

    const int row0 = blockIdx.y * 128;
    const int col0 = blockIdx.x * 128;

    float acc[4][4][4];
#pragma unroll
    for (int mf = 0; mf < 4; mf++)
#pragma unroll
        for (int nf = 0; nf < 4; nf++)
#pragma unroll
            for (int i = 0; i < 4; i++) acc[mf][nf][i] = 0.f;

    // cp.async one 128x32 A tile + 32x128 B tile into buffer bufi
    auto cp_tile = [&](int kt, int bufi) {
        float* as = Asm + bufi * ASZ;
        float* bs = Bsm + bufi * BSZ;
#pragma unroll
        for (int i = 0; i < 4; i++) {
            int idx = tid + i * 256;
            // A: 128 rows x 8 float4
            int ar = idx >> 3, ac = (idx & 7) << 2;
            const float* ga = A + (size_t)(row0 + ar) * K + kt + ac;
            uint32_t sa = (uint32_t)__cvta_generic_to_shared(&as[ar * AS_STRIDE + ac]);
            asm volatile("cp.async.cg.shared.global [%0], [%1], 16;\n"
                         :: "r"(sa), "l"(ga));
            // B: 32 rows x 32 float4
            int br = idx >> 5, bc = (idx & 31) << 2;
            const float* gb = B + (size_t)(kt + br) * N + col0 + bc;
            uint32_t sb = (uint32_t)__cvta_generic_to_shared(&bs[br * BS_STRIDE + bc]);
            asm volatile("cp.async.cg.shared.global [%0], [%1], 16;\n"
                         :: "r"(sb), "l"(gb));
        }
    };

    const int nk = K / 32;
    cp_tile(0, 0);
    asm volatile("cp.async.commit_group;\n");

    int buf = 0;
    for (int t = 0; t < nk; t++) {
        if (t + 1 < nk) cp_tile((t + 1) * 32, buf ^ 1);
        asm volatile("cp.async.commit_group;\n");
        asm volatile("cp.async.wait_group 1;\n");
        __syncthreads();

        const float* as = Asm + buf * ASZ;
        const float* bs = Bsm + buf * BSZ;
#pragma unroll
        for (int kk = 0; kk < 32; kk += 8) {
            uint32_t af[4][4], bf[4][2];
#pragma unroll
            for (int mf = 0; mf < 4; mf++) {
                int bm = wm * 64 + mf * 16 + r;
                af[mf][0] = f2tf32(as[(bm    ) * AS_STRIDE + kk + cq    ]);
                af[mf][1] = f2tf32(as[(bm + 8) * AS_STRIDE + kk + cq    ]);
                af[mf][2] = f2tf32(as[(bm    ) * AS_STRIDE + kk + cq + 4]);
                af[mf][3] = f2tf32(as[(bm + 8) * AS_STRIDE + kk + cq + 4]);
            }
#pragma unroll
            for (int nf = 0; nf < 4; nf++) {
                int bn = wn * 32 + nf * 8 + r;
                bf[nf][0] = f2tf32(bs[(kk + cq    ) * BS_STRIDE + bn]);
                bf[nf][1] = f2tf32(bs[(kk + cq + 4) * BS_STRIDE + bn]);
            }
#pragma unroll
            for (int mf = 0; mf < 4; mf++)
#pragma unroll
                for (int nf = 0; nf < 4; nf++)
                    MMA_TF32(acc[mf][nf], af[mf], bf[nf]);
        }
        __syncthreads();
        buf ^= 1;
    }

    // Epilogue: c0,c1 at (row, 2c), (row, 2c+1); c2,c3 at (row+8, ...)
#pragma unroll
    for (int mf = 0; mf < 4; mf++) {
#pragma unroll
        for (int nf = 0; nf < 4; nf++) {
            int row = row0 + wm * 64 + mf * 16 + r;
            int col = col0 + wn * 32 + nf * 8 + cq * 2;
            float2 v0 = make_float2(acc[mf][nf][0], acc[mf][nf][1]);
            float2 v1 = make_float2(acc[mf][nf][2], acc[mf][nf][3]);
            if (R) {
                float2 r0 = *(const float2*)&R[(size_t)row * N + col];
                float2 r1 = *(const float2*)&R[(size_t)(row + 8) * N + col];
                v0.x += r0.x; v0.y += r0.y;
                v1.x += r1.x; v1.y += r1.y;
            }
            *(float2*)&C[(size_t)row * N + col]       = v0;
            *(float2*)&C[(size_t)(row + 8) * N + col] = v1;
        }
    }
}

// ---------------------------------------------------------------------------
// Per-head RMSNorm over DH=128, in-place. One warp per head-row.
// ---------------------------------------------------------------------------
__global__ __launch_bounds__(256) void rmsnorm_heads(
    float* __restrict__ t, const float* __restrict__ gamma, int nrows)
{
    int row  = blockIdx.x * 8 + (threadIdx.x >> 5);
    if (row >= nrows) return;
    int lane = threadIdx.x & 31;

    float4 v = *(float4*)&t[(size_t)row * DH + lane * 4];
    float ss = v.x * v.x + v.y * v.y + v.z * v.z + v.w * v.w;
#pragma unroll
    for (int m = 16; m; m >>= 1) ss += __shfl_xor_sync(0xffffffffu, ss, m);
    float r = rsqrtf(ss * (1.0f / DH) + 1e-8f);

    float4 g = *(const float4*)&gamma[lane * 4];
    v.x *= r * g.x; v.y *= r * g.y; v.z *= r * g.z; v.w *= r * g.w;
    *(float4*)&t[(size_t)row * DH + lane * 4] = v;
}

// ---------------------------------------------------------------------------
// Flash-style causal attention, fp32 (unchanged this round).
// ---------------------------------------------------------------------------
#define BQ 64
#define BKT 64

__global__ __launch_bounds__(256) void flash_attn(
    const float* __restrict__ Q, const float* __restrict__ K,
    const float* __restrict__ V, float* __restrict__ O)
{
    extern __shared__ float sm[];
    float* Qs  = sm;                 // 64*128
    float* KVs = Qs + BQ * DH;       // 64*128 (K then reused for V)
    float* Ps  = KVs + BKT * DH;     // 64*64

    const int bq = blockIdx.x;
    const int h  = blockIdx.y;
    const int b  = blockIdx.z;
    const int kvh = h >> 2;          // NH/NKV = 4

    const int tid = threadIdx.x;
    const int ty  = tid >> 4;        // 0..15 -> 4 query rows
    const int tx  = tid & 15;        // 0..15

    const float* Qg = Q + ((size_t)b * S_LEN * NH  + h)   * DH;
    const float* Kg = K + ((size_t)b * S_LEN * NKV + kvh) * DH;
    const float* Vg = V + ((size_t)b * S_LEN * NKV + kvh) * DH;
    float*       Og = O + ((size_t)b * S_LEN * NH  + h)   * DH;

    const float qscale = 0.08838834764831845f;  // 1/sqrt(DH)

    for (int i = tid; i < BQ * (DH / 4); i += 256) {
        int r  = i >> 5;
        int c4 = (i & 31) << 2;
        float4 v = *(const float4*)&Qg[(size_t)(bq * BQ + r) * DMODEL + c4];
        v.x *= qscale; v.y *= qscale; v.z *= qscale; v.w *= qscale;
        *(float4*)&Qs[r * DH + c4] = v;
    }

    float m[4], l[4];
    float acc[4][8];
#pragma unroll
    for (int r = 0; r < 4; r++) {
        m[r] = -1e30f; l[r] = 0.f;
#pragma unroll
        for (int j = 0; j < 8; j++) acc[r][j] = 0.f;
    }

    for (int t = 0; t <= bq; t++) {
        __syncthreads();
        for (int i = tid; i < BKT * (DH / 4); i += 256) {
            int r  = i >> 5;
            int c4 = (i & 31) << 2;
            *(float4*)&KVs[r * DH + c4] =
                *(const float4*)&Kg[(size_t)(t * BKT + r) * KVD + c4];
        }
        __syncthreads();

        float s[4][4];
#pragma unroll
        for (int r = 0; r < 4; r++)
#pragma unroll
            for (int c = 0; c < 4; c++) s[r][c] = 0.f;

        for (int k = 0; k < DH; k += 4) {
            float4 qa[4], kb[4];
#pragma unroll
            for (int r = 0; r < 4; r++)
                qa[r] = *(float4*)&Qs[(ty * 4 + r) * DH + k];
#pragma unroll
            for (int c = 0; c < 4; c++)
                kb[c] = *(float4*)&KVs[(tx * 4 + c) * DH + k];
#pragma unroll
            for (int r = 0; r < 4; r++)
#pragma unroll
                for (int c = 0; c < 4; c++) {
                    s[r][c] = fmaf(qa[r].x, kb[c].x, s[r][c]);
                    s[r][c] = fmaf(qa[r].y, kb[c].y, s[r][c]);
                    s[r][c] = fmaf(qa[r].z, kb[c].z, s[r][c]);
                    s[r][c] = fmaf(qa[r].w, kb[c].w, s[r][c]);
                }
        }

        if (t == bq) {
#pragma unroll
            for (int r = 0; r < 4; r++)
#pragma unroll
                for (int c = 0; c < 4; c++)
                    if (tx * 4 + c > ty * 4 + r) s[r][c] = -1e30f;
        }

#pragma unroll
        for (int r = 0; r < 4; r++) {
            float mx = fmaxf(fmaxf(s[r][0], s[r][1]), fmaxf(s[r][2], s[r][3]));
#pragma unroll
            for (int d = 1; d < 16; d <<= 1)
                mx = fmaxf(mx, __shfl_xor_sync(0xffffffffu, mx, d));
            float mn = fmaxf(m[r], mx);
            float sc = __expf(m[r] - mn);
            m[r] = mn;
            float rs = 0.f;
#pragma unroll
            for (int c = 0; c < 4; c++) {
                float p = __expf(s[r][c] - mn);
                s[r][c] = p;
                rs += p;
            }
#pragma unroll
            for (int d = 1; d < 16; d <<= 1)
                rs += __shfl_xor_sync(0xffffffffu, rs, d);
            l[r] = l[r] * sc + rs;
#pragma unroll
            for (int j = 0; j < 8; j++) acc[r][j] *= sc;
#pragma unroll
            for (int c = 0; c < 4; c++)
                Ps[(ty * 4 + r) * BKT + tx * 4 + c] = s[r][c];
        }
        __syncthreads();

        for (int i = tid; i < BKT * (DH / 4); i += 256) {
            int r  = i >> 5;
            int c4 = (i & 31) << 2;
            *(float4*)&KVs[r * DH + c4] =
                *(const float4*)&Vg[(size_t)(t * BKT + r) * KVD + c4];
        }
        __syncthreads();

        for (int k = 0; k < BKT; k++) {
            float p0 = Ps[(ty * 4 + 0) * BKT + k];
            float p1 = Ps[(ty * 4 + 1) * BKT + k];
            float p2 = Ps[(ty * 4 + 2) * BKT + k];
            float p3 = Ps[(ty * 4 + 3) * BKT + k];
            float4 v0 = *(float4*)&KVs[k * DH + tx * 8];
            float4 v1 = *(float4*)&KVs[k * DH + tx * 8 + 4];
            float pv[4] = {p0, p1, p2, p3};
#pragma unroll
            for (int r = 0; r < 4; r++) {
                acc[r][0] = fmaf(pv[r], v0.x, acc[r][0]);
                acc[r][1] = fmaf(pv[r], v0.y, acc[r][1]);
                acc[r][2] = fmaf(pv[r], v0.z, acc[r][2]);
                acc[r][3] = fmaf(pv[r], v0.w, acc[r][3]);
                acc[r][4] = fmaf(pv[r], v1.x, acc[r][4]);
                acc[r][5] = fmaf(pv[r], v1.y, acc[r][5]);
                acc[r][6] = fmaf(pv[r], v1.z, acc[r][6]);
                acc[r][7] = fmaf(pv[r], v1.w, acc[r][7]);
            }
        }
    }

#pragma unroll
    for (int r = 0; r < 4; r++) {
        float inv = 1.f / l[r];
        float4 o0, o1;
        o0.x = acc[r][0] * inv; o0.y = acc[r][1] * inv;
        o0.z = acc[r][2] * inv; o0.w = acc[r][3] * inv;
        o1.x = acc[r][4] * inv; o1.y = acc[r][5] * inv;
        o1.z = acc[r][6] * inv; o1.w = acc[r][7] * inv;
        size_t orow = (size_t)(bq * BQ + ty * 4 + r) * DMODEL + tx * 8;
        *(float4*)&Og[orow]     = o0;
        *(float4*)&Og[orow + 4] = o1;
    }
}

// ---------------------------------------------------------------------------
extern "C" void kernel_launch(void* const* d_in, const int* in_sizes, int n_in,
                              void* d_out, int out_size)
{
    const float* x  = (const float*)d_in[0];
    const float* Wq = (const float*)d_in[1];
    const float* Wk = (const float*)d_in[2];
    const float* Wv = (const float*)d_in[3];
    const float* Wo = (const float*)d_in[4];
    const float* qg = (const float*)d_in[5];
    const float* kg = (const float*)d_in[6];
    float* out = (float*)d_out;

    float *pq, *pk, *pv, *po;
    cudaGetSymbolAddress((void**)&pq, g_q);
    cudaGetSymbolAddress((void**)&pk, g_k);
    cudaGetSymbolAddress((void**)&pv, g_v);
    cudaGetSymbolAddress((void**)&po, g_o);

    static bool attr_set = false;
    if (!attr_set) {
        cudaFuncSetAttribute(tf32gemm,
            cudaFuncAttributeMaxDynamicSharedMemorySize, GEMM_SMEM);
        attr_set = true;
    }

    // QKV projections (TF32 tensor cores)
    tf32gemm<<<dim3(DMODEL / 128, NTOK / 128), 256, GEMM_SMEM>>>(x, Wq, pq, nullptr, NTOK, DMODEL, DMODEL);
    tf32gemm<<<dim3(KVD    / 128, NTOK / 128), 256, GEMM_SMEM>>>(x, Wk, pk, nullptr, NTOK, KVD,    DMODEL);
    tf32gemm<<<dim3(KVD    / 128, NTOK / 128), 256, GEMM_SMEM>>>(x, Wv, pv, nullptr, NTOK, KVD,    DMODEL);

    // Per-head RMSNorm (in place)
    rmsnorm_heads<<<(NTOK * NH  + 7) / 8, 256>>>(pq, qg, NTOK * NH);
    rmsnorm_heads<<<(NTOK * NKV + 7) / 8, 256>>>(pk, kg, NTOK * NKV);

    // Causal GQA attention
    int smem = (BQ * DH + BKT * DH + BQ * BKT) * sizeof(float);  // 80 KB
    cudaFuncSetAttribute(flash_attn, cudaFuncAttributeMaxDynamicSharedMemorySize, smem);
    flash_attn<<<dim3(S_LEN / BQ, NH, NB), 256, smem>>>(pq, pk, pv, po);

    // Output projection + residual (TF32 tensor cores)
    tf32gemm<<<dim3(DMODEL / 128, NTOK / 128), 256, GEMM_SMEM>>>(po, Wo, out, x, NTOK, DMODEL, DMODEL);
}

// round 7
// speedup vs baseline: 5.4948x; 3.9127x over previous
#include <cuda_runtime.h>
#include <cuda_bf16.h>
#include <cstdint>
#include <cstddef>

// Problem constants
#define S_LEN  2048
#define NB     2
#define NH     16
#define NKV    4
#define DH     128
#define DMODEL 2048   // NH*DH
#define KVD    512    // NKV*DH
#define NTOK   (NB*S_LEN)   // 4096

// Scratch (device globals — no allocations allowed)
__device__ float g_q[(size_t)NTOK * DMODEL];
__device__ float g_k[(size_t)NTOK * KVD];
__device__ float g_v[(size_t)NTOK * KVD];
__device__ float g_o[(size_t)NTOK * DMODEL];

__device__ __forceinline__ uint32_t f2tf32(float x) {
    uint32_t y;
    asm("cvt.rna.tf32.f32 %0, %1;" : "=r"(y) : "f"(x));
    return y;
}

#define MMA_TF32(d, a, b)                                               \
    asm volatile(                                                       \
        "mma.sync.aligned.m16n8k8.row.col.f32.tf32.tf32.f32 "           \
        "{%0,%1,%2,%3}, {%4,%5,%6,%7}, {%8,%9}, {%0,%1,%2,%3};\n"       \
        : "+f"(d[0]), "+f"(d[1]), "+f"(d[2]), "+f"(d[3])                \
        : "r"(a[0]), "r"(a[1]), "r"(a[2]), "r"(a[3]),                   \
          "r"(b[0]), "r"(b[1]))

// ---------------------------------------------------------------------------
// TF32 tensor-core GEMM: C[M,N] = A[M,K] @ B[K,N] (+ R if R != nullptr)
// BM=BN=128, BK=32, 256 threads (8 warps), warp tile 64x32 via m16n8k8 tf32.
// ---------------------------------------------------------------------------
#define AS_STRIDE 36
#define BS_STRIDE 136
#define ASZ (128 * AS_STRIDE)
#define BSZ (32  * BS_STRIDE)
#define GEMM_SMEM ((2 * (ASZ + BSZ)) * (int)sizeof(float))  // 71680 B

__global__ __launch_bounds__(256, 2) void tf32gemm(
    const float* __restrict__ A, const float* __restrict__ B,
    float* __restrict__ C, const float* __restrict__ R,
    int M, int N, int K)
{
    extern __shared__ float sm[];
    float* Asm = sm;
    float* Bsm = sm + 2 * ASZ;

    const int tid  = threadIdx.x;
    const int wid  = tid >> 5;
    const int lane = tid & 31;
    const int wm   = wid >> 2;
    const int wn   = wid & 3;
    const int r    = lane >> 2;
    const int cq   = lane & 3;

    const int row0 = blockIdx.y * 128;
    const int col0 = blockIdx.x * 128;

    float acc[4][4][4];
#pragma unroll
    for (int mf = 0; mf < 4; mf++)
#pragma unroll
        for (int nf = 0; nf < 4; nf++)
#pragma unroll
            for (int i = 0; i < 4; i++) acc[mf][nf][i] = 0.f;

    auto cp_tile = [&](int kt, int bufi) {
        float* as = Asm + bufi * ASZ;
        float* bs = Bsm + bufi * BSZ;
#pragma unroll
        for (int i = 0; i < 4; i++) {
            int idx = tid + i * 256;
            int ar = idx >> 3, ac = (idx & 7) << 2;
            const float* ga = A + (size_t)(row0 + ar) * K + kt + ac;
            uint32_t sa = (uint32_t)__cvta_generic_to_shared(&as[ar * AS_STRIDE + ac]);
            asm volatile("cp.async.cg.shared.global [%0], [%1], 16;\n"
                         :: "r"(sa), "l"(ga));
            int br = idx >> 5, bc = (idx & 31) << 2;
            const float* gb = B + (size_t)(kt + br) * N + col0 + bc;
            uint32_t sb = (uint32_t)__cvta_generic_to_shared(&bs[br * BS_STRIDE + bc]);
            asm volatile("cp.async.cg.shared.global [%0], [%1], 16;\n"
                         :: "r"(sb), "l"(gb));
        }
    };

    const int nk = K / 32;
    cp_tile(0, 0);
    asm volatile("cp.async.commit_group;\n");

    int buf = 0;
    for (int t = 0; t < nk; t++) {
        if (t + 1 < nk) cp_tile((t + 1) * 32, buf ^ 1);
        asm volatile("cp.async.commit_group;\n");
        asm volatile("cp.async.wait_group 1;\n");
        __syncthreads();

        const float* as = Asm + buf * ASZ;
        const float* bs = Bsm + buf * BSZ;
#pragma unroll
        for (int kk = 0; kk < 32; kk += 8) {
            uint32_t af[4][4], bf[4][2];
#pragma unroll
            for (int mf = 0; mf < 4; mf++) {
                int bm = wm * 64 + mf * 16 + r;
                af[mf][0] = f2tf32(as[(bm    ) * AS_STRIDE + kk + cq    ]);
                af[mf][1] = f2tf32(as[(bm + 8) * AS_STRIDE + kk + cq    ]);
                af[mf][2] = f2tf32(as[(bm    ) * AS_STRIDE + kk + cq + 4]);
                af[mf][3] = f2tf32(as[(bm + 8) * AS_STRIDE + kk + cq + 4]);
            }
#pragma unroll
            for (int nf = 0; nf < 4; nf++) {
                int bn = wn * 32 + nf * 8 + r;
                bf[nf][0] = f2tf32(bs[(kk + cq    ) * BS_STRIDE + bn]);
                bf[nf][1] = f2tf32(bs[(kk + cq + 4) * BS_STRIDE + bn]);
            }
#pragma unroll
            for (int mf = 0; mf < 4; mf++)
#pragma unroll
                for (int nf = 0; nf < 4; nf++)
                    MMA_TF32(acc[mf][nf], af[mf], bf[nf]);
        }
        __syncthreads();
        buf ^= 1;
    }

#pragma unroll
    for (int mf = 0; mf < 4; mf++) {
#pragma unroll
        for (int nf = 0; nf < 4; nf++) {
            int row = row0 + wm * 64 + mf * 16 + r;
            int col = col0 + wn * 32 + nf * 8 + cq * 2;
            float2 v0 = make_float2(acc[mf][nf][0], acc[mf][nf][1]);
            float2 v1 = make_float2(acc[mf][nf][2], acc[mf][nf][3]);
            if (R) {
                float2 r0 = *(const float2*)&R[(size_t)row * N + col];
                float2 r1 = *(const float2*)&R[(size_t)(row + 8) * N + col];
                v0.x += r0.x; v0.y += r0.y;
                v1.x += r1.x; v1.y += r1.y;
            }
            *(float2*)&C[(size_t)row * N + col]       = v0;
            *(float2*)&C[(size_t)(row + 8) * N + col] = v1;
        }
    }
}

// ---------------------------------------------------------------------------
// Per-head RMSNorm over DH=128, in-place. One warp per head-row.
// ---------------------------------------------------------------------------
__global__ __launch_bounds__(256) void rmsnorm_heads(
    float* __restrict__ t, const float* __restrict__ gamma, int nrows)
{
    int row  = blockIdx.x * 8 + (threadIdx.x >> 5);
    if (row >= nrows) return;
    int lane = threadIdx.x & 31;

    float4 v = *(float4*)&t[(size_t)row * DH + lane * 4];
    float ss = v.x * v.x + v.y * v.y + v.z * v.z + v.w * v.w;
#pragma unroll
    for (int m = 16; m; m >>= 1) ss += __shfl_xor_sync(0xffffffffu, ss, m);
    float r = rsqrtf(ss * (1.0f / DH) + 1e-8f);

    float4 g = *(const float4*)&gamma[lane * 4];
    v.x *= r * g.x; v.y *= r * g.y; v.z *= r * g.z; v.w *= r * g.w;
    *(float4*)&t[(size_t)row * DH + lane * 4] = v;
}

// ---------------------------------------------------------------------------
// TF32 tensor-core causal flash attention.
// BQ=128 q rows per CTA, BK=64 key tiles. 8 warps, warp = 16 q-rows x full
// tile width. Q held in registers as tf32; K/V/P raw fp32 in smem consumed
// by MMA with HW truncation. cp.async double-stream: V_t overlaps QK^T,
// K_{t+1} overlaps PV. Grid: (S/128, NH, NB).
// ---------------------------------------------------------------------------
#define ATT_BQ   128
#define ATT_BK   64
#define KS_STRIDE 132   // K tile: [key n][dh k]
#define VS_STRIDE 136   // V tile: [key k][dh n]
#define PS_STRIDE 68    // P tile: [q row][key k]
#define ATT_SMEM ((64 * KS_STRIDE + 64 * VS_STRIDE + 128 * PS_STRIDE) * (int)sizeof(float)) // 103424

__global__ __launch_bounds__(256) void flash_attn_tf32(
    const float* __restrict__ Q, const float* __restrict__ K,
    const float* __restrict__ V, float* __restrict__ O)
{
    extern __shared__ float sm[];
    float* Ks = sm;                          // 64*132
    float* Vs = Ks + 64 * KS_STRIDE;         // 64*136 (also Q staging)
    float* Ps = Vs + 64 * VS_STRIDE;         // 128*68

    const int bq  = blockIdx.x;
    const int h   = blockIdx.y;
    const int b   = blockIdx.z;
    const int kvh = h >> 2;

    const int tid  = threadIdx.x;
    const int wid  = tid >> 5;
    const int lane = tid & 31;
    const int r    = lane >> 2;   // 0..7
    const int cq   = lane & 3;    // 0..3
    const int band = wid * 16;

    const float* Qg = Q + (size_t)b * S_LEN * DMODEL + h * DH;
    const float* Kg = K + (size_t)b * S_LEN * KVD + kvh * DH;
    const float* Vg = V + (size_t)b * S_LEN * KVD + kvh * DH;
    float*       Og = O + (size_t)b * S_LEN * DMODEL + h * DH;

    const int q0 = bq * ATT_BQ;
    const float qscale = 0.08838834764831845f;  // 1/sqrt(DH)

    // Prefetch K tile 0 (independent of Q staging buffer)
    {
#pragma unroll
        for (int i = tid; i < 2048; i += 256) {
            int rr = i >> 5, c4 = (i & 31) << 2;
            const float* g = Kg + (size_t)rr * KVD + c4;
            uint32_t s = (uint32_t)__cvta_generic_to_shared(&Ks[rr * KS_STRIDE + c4]);
            asm volatile("cp.async.cg.shared.global [%0], [%1], 16;\n" :: "r"(s), "l"(g));
        }
        asm volatile("cp.async.commit_group;\n");
    }

    // Stage Q (scaled) through Vs in two 64-row chunks; convert to tf32 regs.
    uint32_t qf[16][4];
#pragma unroll
    for (int chunk = 0; chunk < 2; chunk++) {
        __syncthreads();
        for (int i = tid; i < 2048; i += 256) {
            int rr = i >> 5, c4 = (i & 31) << 2;
            float4 v = *(const float4*)&Qg[(size_t)(q0 + chunk * 64 + rr) * DMODEL + c4];
            v.x *= qscale; v.y *= qscale; v.z *= qscale; v.w *= qscale;
            *(float4*)&Vs[rr * KS_STRIDE + c4] = v;   // stride 132 staging
        }
        __syncthreads();
        if ((wid >> 2) == chunk) {
            int lr = (wid & 3) * 16;
#pragma unroll
            for (int ks = 0; ks < 16; ks++) {
                qf[ks][0] = f2tf32(Vs[(lr + r    ) * KS_STRIDE + ks * 8 + cq    ]);
                qf[ks][1] = f2tf32(Vs[(lr + r + 8) * KS_STRIDE + ks * 8 + cq    ]);
                qf[ks][2] = f2tf32(Vs[(lr + r    ) * KS_STRIDE + ks * 8 + cq + 4]);
                qf[ks][3] = f2tf32(Vs[(lr + r + 8) * KS_STRIDE + ks * 8 + cq + 4]);
            }
        }
    }

    float oacc[16][4];
#pragma unroll
    for (int nf = 0; nf < 16; nf++)
#pragma unroll
        for (int j = 0; j < 4; j++) oacc[nf][j] = 0.f;
    float m0 = -1e30f, m1 = -1e30f, l0 = 0.f, l1 = 0.f;

    const uint32_t* Ku = (const uint32_t*)Ks;
    const uint32_t* Vu = (const uint32_t*)Vs;
    const uint32_t* Pu = (const uint32_t*)Ps;

    const int ntiles = 2 * bq + 2;
    for (int t = 0; t < ntiles; t++) {
        asm volatile("cp.async.wait_group 0;\n");
        __syncthreads();               // K_t resident; prev PV done with Vs/Ps

        // Prefetch V_t (overlaps QK^T)
        for (int i = tid; i < 2048; i += 256) {
            int rr = i >> 5, c4 = (i & 31) << 2;
            const float* g = Vg + (size_t)(t * ATT_BK + rr) * KVD + c4;
            uint32_t s = (uint32_t)__cvta_generic_to_shared(&Vs[rr * VS_STRIDE + c4]);
            asm volatile("cp.async.cg.shared.global [%0], [%1], 16;\n" :: "r"(s), "l"(g));
        }
        asm volatile("cp.async.commit_group;\n");

        // S = Q K^T  (warp: 16 rows x 64 cols)
        float sacc[8][4];
#pragma unroll
        for (int nf = 0; nf < 8; nf++)
#pragma unroll
            for (int j = 0; j < 4; j++) sacc[nf][j] = 0.f;

#pragma unroll
        for (int ks = 0; ks < 16; ks++) {
#pragma unroll
            for (int nf = 0; nf < 8; nf++) {
                uint32_t bf[2];
                bf[0] = Ku[(nf * 8 + r) * KS_STRIDE + ks * 8 + cq    ];
                bf[1] = Ku[(nf * 8 + r) * KS_STRIDE + ks * 8 + cq + 4];
                MMA_TF32(sacc[nf], qf[ks], bf);
            }
        }

        // Causal mask (only last two tiles touch the diagonal)
        if (t >= 2 * bq) {
            int gq0 = q0 + band + r;
            int gq1 = gq0 + 8;
#pragma unroll
            for (int nf = 0; nf < 8; nf++) {
                int gk = t * ATT_BK + nf * 8 + 2 * cq;
                if (gk     > gq0) sacc[nf][0] = -1e30f;
                if (gk + 1 > gq0) sacc[nf][1] = -1e30f;
                if (gk     > gq1) sacc[nf][2] = -1e30f;
                if (gk + 1 > gq1) sacc[nf][3] = -1e30f;
            }
        }

        // Row max (warp-local: lanes sharing r differ in bits 0-1)
        float mx0 = -1e30f, mx1 = -1e30f;
#pragma unroll
        for (int nf = 0; nf < 8; nf++) {
            mx0 = fmaxf(mx0, fmaxf(sacc[nf][0], sacc[nf][1]));
            mx1 = fmaxf(mx1, fmaxf(sacc[nf][2], sacc[nf][3]));
        }
        mx0 = fmaxf(mx0, __shfl_xor_sync(0xffffffffu, mx0, 1));
        mx0 = fmaxf(mx0, __shfl_xor_sync(0xffffffffu, mx0, 2));
        mx1 = fmaxf(mx1, __shfl_xor_sync(0xffffffffu, mx1, 1));
        mx1 = fmaxf(mx1, __shfl_xor_sync(0xffffffffu, mx1, 2));

        float mn0 = fmaxf(m0, mx0), mn1 = fmaxf(m1, mx1);
        float sc0 = __expf(m0 - mn0), sc1 = __expf(m1 - mn1);
        m0 = mn0; m1 = mn1;

        float rs0 = 0.f, rs1 = 0.f;
#pragma unroll
        for (int nf = 0; nf < 8; nf++) {
            float p0 = __expf(sacc[nf][0] - mn0);
            float p1 = __expf(sacc[nf][1] - mn0);
            float p2 = __expf(sacc[nf][2] - mn1);
            float p3 = __expf(sacc[nf][3] - mn1);
            rs0 += p0 + p1; rs1 += p2 + p3;
            *(float2*)&Ps[(band + r    ) * PS_STRIDE + nf * 8 + 2 * cq] = make_float2(p0, p1);
            *(float2*)&Ps[(band + r + 8) * PS_STRIDE + nf * 8 + 2 * cq] = make_float2(p2, p3);
        }
        rs0 += __shfl_xor_sync(0xffffffffu, rs0, 1);
        rs0 += __shfl_xor_sync(0xffffffffu, rs0, 2);
        rs1 += __shfl_xor_sync(0xffffffffu, rs1, 1);
        rs1 += __shfl_xor_sync(0xffffffffu, rs1, 2);
        l0 = l0 * sc0 + rs0;
        l1 = l1 * sc1 + rs1;

        // Rescale O accumulators
#pragma unroll
        for (int nf = 0; nf < 16; nf++) {
            oacc[nf][0] *= sc0; oacc[nf][1] *= sc0;
            oacc[nf][2] *= sc1; oacc[nf][3] *= sc1;
        }

        asm volatile("cp.async.wait_group 0;\n");
        __syncthreads();               // V_t resident; all warps past K reads & P stores

        // Prefetch K_{t+1} (overlaps PV)
        if (t + 1 < ntiles) {
            for (int i = tid; i < 2048; i += 256) {
                int rr = i >> 5, c4 = (i & 31) << 2;
                const float* g = Kg + (size_t)((t + 1) * ATT_BK + rr) * KVD + c4;
                uint32_t s = (uint32_t)__cvta_generic_to_shared(&Ks[rr * KS_STRIDE + c4]);
                asm volatile("cp.async.cg.shared.global [%0], [%1], 16;\n" :: "r"(s), "l"(g));
            }
            asm volatile("cp.async.commit_group;\n");
        }

        // O += P V   (warp: 16 rows x 128 dh cols, K=64 keys)
#pragma unroll
        for (int ks = 0; ks < 8; ks++) {
            uint32_t af[4];
            af[0] = Pu[(band + r    ) * PS_STRIDE + ks * 8 + cq    ];
            af[1] = Pu[(band + r + 8) * PS_STRIDE + ks * 8 + cq    ];
            af[2] = Pu[(band + r    ) * PS_STRIDE + ks * 8 + cq + 4];
            af[3] = Pu[(band + r + 8) * PS_STRIDE + ks * 8 + cq + 4];
#pragma unroll
            for (int nf = 0; nf < 16; nf++) {
                uint32_t bf[2];
                bf[0] = Vu[(ks * 8 + cq    ) * VS_STRIDE + nf * 8 + r];
                bf[1] = Vu[(ks * 8 + cq + 4) * VS_STRIDE + nf * 8 + r];
                MMA_TF32(oacc[nf], af, bf);
            }
        }
    }

    // Normalize and write out
    float inv0 = 1.f / l0, inv1 = 1.f / l1;
    size_t row0 = (size_t)(q0 + band + r) * DMODEL;
    size_t row1 = (size_t)(q0 + band + r + 8) * DMODEL;
#pragma unroll
    for (int nf = 0; nf < 16; nf++) {
        int col = nf * 8 + 2 * cq;
        *(float2*)&Og[row0 + col] = make_float2(oacc[nf][0] * inv0, oacc[nf][1] * inv0);
        *(float2*)&Og[row1 + col] = make_float2(oacc[nf][2] * inv1, oacc[nf][3] * inv1);
    }
}

// ---------------------------------------------------------------------------
extern "C" void kernel_launch(void* const* d_in, const int* in_sizes, int n_in,
                              void* d_out, int out_size)
{
    const float* x  = (const float*)d_in[0];
    const float* Wq = (const float*)d_in[1];
    const float* Wk = (const float*)d_in[2];
    const float* Wv = (const float*)d_in[3];
    const float* Wo = (const float*)d_in[4];
    const float* qg = (const float*)d_in[5];
    const float* kg = (const float*)d_in[6];
    float* out = (float*)d_out;

    float *pq, *pk, *pv, *po;
    cudaGetSymbolAddress((void**)&pq, g_q);
    cudaGetSymbolAddress((void**)&pk, g_k);
    cudaGetSymbolAddress((void**)&pv, g_v);
    cudaGetSymbolAddress((void**)&po, g_o);

    cudaFuncSetAttribute(tf32gemm,
        cudaFuncAttributeMaxDynamicSharedMemorySize, GEMM_SMEM);
    cudaFuncSetAttribute(flash_attn_tf32,
        cudaFuncAttributeMaxDynamicSharedMemorySize, ATT_SMEM);

    // QKV projections (TF32 tensor cores)
    tf32gemm<<<dim3(DMODEL / 128, NTOK / 128), 256, GEMM_SMEM>>>(x, Wq, pq, nullptr, NTOK, DMODEL, DMODEL);
    tf32gemm<<<dim3(KVD    / 128, NTOK / 128), 256, GEMM_SMEM>>>(x, Wk, pk, nullptr, NTOK, KVD,    DMODEL);
    tf32gemm<<<dim3(KVD    / 128, NTOK / 128), 256, GEMM_SMEM>>>(x, Wv, pv, nullptr, NTOK, KVD,    DMODEL);

    // Per-head RMSNorm (in place)
    rmsnorm_heads<<<(NTOK * NH  + 7) / 8, 256>>>(pq, qg, NTOK * NH);
    rmsnorm_heads<<<(NTOK * NKV + 7) / 8, 256>>>(pk, kg, NTOK * NKV);

    // Causal GQA attention (TF32 tensor cores)
    flash_attn_tf32<<<dim3(S_LEN / ATT_BQ, NH, NB), 256, ATT_SMEM>>>(pq, pk, pv, po);

    // Output projection + residual (TF32 tensor cores)
    tf32gemm<<<dim3(DMODEL / 128, NTOK / 128), 256, GEMM_SMEM>>>(po, Wo, out, x, NTOK, DMODEL, DMODEL);
}

// round 8
// speedup vs baseline: 5.9723x; 1.0869x over previous
#include <cuda_runtime.h>
#include <cuda_bf16.h>
#include <cstdint>
#include <cstddef>

// Problem constants
#define S_LEN  2048
#define NB     2
#define NH     16
#define NKV    4
#define DH     128
#define DMODEL 2048   // NH*DH
#define KVD    512    // NKV*DH
#define NTOK   (NB*S_LEN)   // 4096

// Scratch (device globals — no allocations allowed)
__device__ float g_q[(size_t)NTOK * DMODEL];
__device__ float g_k[(size_t)NTOK * KVD];
__device__ float g_v[(size_t)NTOK * KVD];
__device__ float g_o[(size_t)NTOK * DMODEL];

__device__ __forceinline__ uint32_t f2tf32(float x) {
    uint32_t y;
    asm("cvt.rna.tf32.f32 %0, %1;" : "=r"(y) : "f"(x));
    return y;
}

#define MMA_TF32(d, a, b)                                               \
    asm volatile(                                                       \
        "mma.sync.aligned.m16n8k8.row.col.f32.tf32.tf32.f32 "           \
        "{%0,%1,%2,%3}, {%4,%5,%6,%7}, {%8,%9}, {%0,%1,%2,%3};\n"       \
        : "+f"(d[0]), "+f"(d[1]), "+f"(d[2]), "+f"(d[3])                \
        : "r"(a[0]), "r"(a[1]), "r"(a[2]), "r"(a[3]),                   \
          "r"(b[0]), "r"(b[1]))

// ---------------------------------------------------------------------------
// TF32 tensor-core GEMM core: C[M,N] = A[M,K] @ B[K,N] (+ R if R != nullptr)
// BM=BN=128, BK=32, 256 threads (8 warps), warp tile 64x32 via m16n8k8 tf32.
// MMA operands are raw fp32 bits (HW tf32 truncation) — no CVT in inner loop.
// ---------------------------------------------------------------------------
#define AS_STRIDE 36
#define BS_STRIDE 136
#define ASZ (128 * AS_STRIDE)
#define BSZ (32  * BS_STRIDE)
#define GEMM_SMEM ((2 * (ASZ + BSZ)) * (int)sizeof(float))  // 71680 B

__device__ __forceinline__ void gemm_core(
    const float* __restrict__ A, const float* __restrict__ B,
    float* __restrict__ C, const float* __restrict__ R,
    int N, int K, int row0, int col0, float* Asm, float* Bsm)
{
    const int tid  = threadIdx.x;
    const int wid  = tid >> 5;
    const int lane = tid & 31;
    const int wm   = wid >> 2;
    const int wn   = wid & 3;
    const int r    = lane >> 2;
    const int cq   = lane & 3;

    float acc[4][4][4];
#pragma unroll
    for (int mf = 0; mf < 4; mf++)
#pragma unroll
        for (int nf = 0; nf < 4; nf++)
#pragma unroll
            for (int i = 0; i < 4; i++) acc[mf][nf][i] = 0.f;

    auto cp_tile = [&](int kt, int bufi) {
        float* as = Asm + bufi * ASZ;
        float* bs = Bsm + bufi * BSZ;
#pragma unroll
        for (int i = 0; i < 4; i++) {
            int idx = tid + i * 256;
            int ar = idx >> 3, ac = (idx & 7) << 2;
            const float* ga = A + (size_t)(row0 + ar) * K + kt + ac;
            uint32_t sa = (uint32_t)__cvta_generic_to_shared(&as[ar * AS_STRIDE + ac]);
            asm volatile("cp.async.cg.shared.global [%0], [%1], 16;\n"
                         :: "r"(sa), "l"(ga));
            int br = idx >> 5, bc = (idx & 31) << 2;
            const float* gb = B + (size_t)(kt + br) * N + col0 + bc;
            uint32_t sb = (uint32_t)__cvta_generic_to_shared(&bs[br * BS_STRIDE + bc]);
            asm volatile("cp.async.cg.shared.global [%0], [%1], 16;\n"
                         :: "r"(sb), "l"(gb));
        }
    };

    const int nk = K / 32;
    cp_tile(0, 0);
    asm volatile("cp.async.commit_group;\n");

    int buf = 0;
    for (int t = 0; t < nk; t++) {
        if (t + 1 < nk) cp_tile((t + 1) * 32, buf ^ 1);
        asm volatile("cp.async.commit_group;\n");
        asm volatile("cp.async.wait_group 1;\n");
        __syncthreads();

        const uint32_t* as = (const uint32_t*)(Asm + buf * ASZ);
        const uint32_t* bs = (const uint32_t*)(Bsm + buf * BSZ);
#pragma unroll
        for (int kk = 0; kk < 32; kk += 8) {
            uint32_t af[4][4], bf[4][2];
#pragma unroll
            for (int mf = 0; mf < 4; mf++) {
                int bm = wm * 64 + mf * 16 + r;
                af[mf][0] = as[(bm    ) * AS_STRIDE + kk + cq    ];
                af[mf][1] = as[(bm + 8) * AS_STRIDE + kk + cq    ];
                af[mf][2] = as[(bm    ) * AS_STRIDE + kk + cq + 4];
                af[mf][3] = as[(bm + 8) * AS_STRIDE + kk + cq + 4];
            }
#pragma unroll
            for (int nf = 0; nf < 4; nf++) {
                int bn = wn * 32 + nf * 8 + r;
                bf[nf][0] = bs[(kk + cq    ) * BS_STRIDE + bn];
                bf[nf][1] = bs[(kk + cq + 4) * BS_STRIDE + bn];
            }
#pragma unroll
            for (int mf = 0; mf < 4; mf++)
#pragma unroll
                for (int nf = 0; nf < 4; nf++)
                    MMA_TF32(acc[mf][nf], af[mf], bf[nf]);
        }
        __syncthreads();
        buf ^= 1;
    }

#pragma unroll
    for (int mf = 0; mf < 4; mf++) {
#pragma unroll
        for (int nf = 0; nf < 4; nf++) {
            int row = row0 + wm * 64 + mf * 16 + r;
            int col = col0 + wn * 32 + nf * 8 + cq * 2;
            float2 v0 = make_float2(acc[mf][nf][0], acc[mf][nf][1]);
            float2 v1 = make_float2(acc[mf][nf][2], acc[mf][nf][3]);
            if (R) {
                float2 r0 = *(const float2*)&R[(size_t)row * N + col];
                float2 r1 = *(const float2*)&R[(size_t)(row + 8) * N + col];
                v0.x += r0.x; v0.y += r0.y;
                v1.x += r1.x; v1.y += r1.y;
            }
            *(float2*)&C[(size_t)row * N + col]       = v0;
            *(float2*)&C[(size_t)(row + 8) * N + col] = v1;
        }
    }
}

// Generic single-matrix GEMM (used for Wo + residual)
__global__ __launch_bounds__(256, 2) void tf32gemm(
    const float* __restrict__ A, const float* __restrict__ B,
    float* __restrict__ C, const float* __restrict__ R,
    int N, int K)
{
    extern __shared__ float sm[];
    gemm_core(A, B, C, R, N, K, blockIdx.y * 128, blockIdx.x * 128,
              sm, sm + 2 * ASZ);
}

// Fused QKV: blockIdx.x 0..15 -> Wq cols, 16..19 -> Wk, 20..23 -> Wv.
__global__ __launch_bounds__(256, 2) void tf32gemm_qkv(
    const float* __restrict__ A,
    const float* __restrict__ Wq, const float* __restrict__ Wk,
    const float* __restrict__ Wv,
    float* __restrict__ Cq, float* __restrict__ Ck, float* __restrict__ Cv)
{
    extern __shared__ float sm[];
    const int bx = blockIdx.x;
    const float* B;
    float* C;
    int N, col0;
    if (bx < 16)      { B = Wq; C = Cq; N = DMODEL; col0 = bx * 128; }
    else if (bx < 20) { B = Wk; C = Ck; N = KVD;    col0 = (bx - 16) * 128; }
    else              { B = Wv; C = Cv; N = KVD;    col0 = (bx - 20) * 128; }
    gemm_core(A, B, C, nullptr, N, DMODEL, blockIdx.y * 128, col0,
              sm, sm + 2 * ASZ);
}

// ---------------------------------------------------------------------------
// Per-head RMSNorm over DH=128, in-place. One warp per head-row.
// ---------------------------------------------------------------------------
__global__ __launch_bounds__(256) void rmsnorm_heads(
    float* __restrict__ t, const float* __restrict__ gamma, int nrows)
{
    int row  = blockIdx.x * 8 + (threadIdx.x >> 5);
    if (row >= nrows) return;
    int lane = threadIdx.x & 31;

    float4 v = *(float4*)&t[(size_t)row * DH + lane * 4];
    float ss = v.x * v.x + v.y * v.y + v.z * v.z + v.w * v.w;
#pragma unroll
    for (int m = 16; m; m >>= 1) ss += __shfl_xor_sync(0xffffffffu, ss, m);
    float r = rsqrtf(ss * (1.0f / DH) + 1e-8f);

    float4 g = *(const float4*)&gamma[lane * 4];
    v.x *= r * g.x; v.y *= r * g.y; v.z *= r * g.z; v.w *= r * g.w;
    *(float4*)&t[(size_t)row * DH + lane * 4] = v;
}

// ---------------------------------------------------------------------------
// TF32 tensor-core causal flash attention (heavy-CTA-first scheduling).
// ---------------------------------------------------------------------------
#define ATT_BQ   128
#define ATT_BK   64
#define KS_STRIDE 132
#define VS_STRIDE 136
#define PS_STRIDE 68
#define ATT_SMEM ((64 * KS_STRIDE + 64 * VS_STRIDE + 128 * PS_STRIDE) * (int)sizeof(float)) // 103424

__global__ __launch_bounds__(256) void flash_attn_tf32(
    const float* __restrict__ Q, const float* __restrict__ K,
    const float* __restrict__ V, float* __restrict__ O)
{
    extern __shared__ float sm[];
    float* Ks = sm;
    float* Vs = Ks + 64 * KS_STRIDE;
    float* Ps = Vs + 64 * VS_STRIDE;

    const int bq  = gridDim.x - 1 - blockIdx.x;   // heavy CTAs scheduled first
    const int h   = blockIdx.y;
    const int b   = blockIdx.z;
    const int kvh = h >> 2;

    const int tid  = threadIdx.x;
    const int wid  = tid >> 5;
    const int lane = tid & 31;
    const int r    = lane >> 2;
    const int cq   = lane & 3;
    const int band = wid * 16;

    const float* Qg = Q + (size_t)b * S_LEN * DMODEL + h * DH;
    const float* Kg = K + (size_t)b * S_LEN * KVD + kvh * DH;
    const float* Vg = V + (size_t)b * S_LEN * KVD + kvh * DH;
    float*       Og = O + (size_t)b * S_LEN * DMODEL + h * DH;

    const int q0 = bq * ATT_BQ;
    const float qscale = 0.08838834764831845f;

    {
#pragma unroll
        for (int i = tid; i < 2048; i += 256) {
            int rr = i >> 5, c4 = (i & 31) << 2;
            const float* g = Kg + (size_t)rr * KVD + c4;
            uint32_t s = (uint32_t)__cvta_generic_to_shared(&Ks[rr * KS_STRIDE + c4]);
            asm volatile("cp.async.cg.shared.global [%0], [%1], 16;\n" :: "r"(s), "l"(g));
        }
        asm volatile("cp.async.commit_group;\n");
    }

    uint32_t qf[16][4];
#pragma unroll
    for (int chunk = 0; chunk < 2; chunk++) {
        __syncthreads();
        for (int i = tid; i < 2048; i += 256) {
            int rr = i >> 5, c4 = (i & 31) << 2;
            float4 v = *(const float4*)&Qg[(size_t)(q0 + chunk * 64 + rr) * DMODEL + c4];
            v.x *= qscale; v.y *= qscale; v.z *= qscale; v.w *= qscale;
            *(float4*)&Vs[rr * KS_STRIDE + c4] = v;
        }
        __syncthreads();
        if ((wid >> 2) == chunk) {
            int lr = (wid & 3) * 16;
#pragma unroll
            for (int ks = 0; ks < 16; ks++) {
                qf[ks][0] = f2tf32(Vs[(lr + r    ) * KS_STRIDE + ks * 8 + cq    ]);
                qf[ks][1] = f2tf32(Vs[(lr + r + 8) * KS_STRIDE + ks * 8 + cq    ]);
                qf[ks][2] = f2tf32(Vs[(lr + r    ) * KS_STRIDE + ks * 8 + cq + 4]);
                qf[ks][3] = f2tf32(Vs[(lr + r + 8) * KS_STRIDE + ks * 8 + cq + 4]);
            }
        }
    }

    float oacc[16][4];
#pragma unroll
    for (int nf = 0; nf < 16; nf++)
#pragma unroll
        for (int j = 0; j < 4; j++) oacc[nf][j] = 0.f;
    float m0 = -1e30f, m1 = -1e30f, l0 = 0.f, l1 = 0.f;

    const uint32_t* Ku = (const uint32_t*)Ks;
    const uint32_t* Vu = (const uint32_t*)Vs;
    const uint32_t* Pu = (const uint32_t*)Ps;

    const int ntiles = 2 * bq + 2;
    for (int t = 0; t < ntiles; t++) {
        asm volatile("cp.async.wait_group 0;\n");
        __syncthreads();

        for (int i = tid; i < 2048; i += 256) {
            int rr = i >> 5, c4 = (i & 31) << 2;
            const float* g = Vg + (size_t)(t * ATT_BK + rr) * KVD + c4;
            uint32_t s = (uint32_t)__cvta_generic_to_shared(&Vs[rr * VS_STRIDE + c4]);
            asm volatile("cp.async.cg.shared.global [%0], [%1], 16;\n" :: "r"(s), "l"(g));
        }
        asm volatile("cp.async.commit_group;\n");

        float sacc[8][4];
#pragma unroll
        for (int nf = 0; nf < 8; nf++)
#pragma unroll
            for (int j = 0; j < 4; j++) sacc[nf][j] = 0.f;

#pragma unroll
        for (int ks = 0; ks < 16; ks++) {
#pragma unroll
            for (int nf = 0; nf < 8; nf++) {
                uint32_t bf[2];
                bf[0] = Ku[(nf * 8 + r) * KS_STRIDE + ks * 8 + cq    ];
                bf[1] = Ku[(nf * 8 + r) * KS_STRIDE + ks * 8 + cq + 4];
                MMA_TF32(sacc[nf], qf[ks], bf);
            }
        }

        if (t >= 2 * bq) {
            int gq0 = q0 + band + r;
            int gq1 = gq0 + 8;
#pragma unroll
            for (int nf = 0; nf < 8; nf++) {
                int gk = t * ATT_BK + nf * 8 + 2 * cq;
                if (gk     > gq0) sacc[nf][0] = -1e30f;
                if (gk + 1 > gq0) sacc[nf][1] = -1e30f;
                if (gk     > gq1) sacc[nf][2] = -1e30f;
                if (gk + 1 > gq1) sacc[nf][3] = -1e30f;
            }
        }

        float mx0 = -1e30f, mx1 = -1e30f;
#pragma unroll
        for (int nf = 0; nf < 8; nf++) {
            mx0 = fmaxf(mx0, fmaxf(sacc[nf][0], sacc[nf][1]));
            mx1 = fmaxf(mx1, fmaxf(sacc[nf][2], sacc[nf][3]));
        }
        mx0 = fmaxf(mx0, __shfl_xor_sync(0xffffffffu, mx0, 1));
        mx0 = fmaxf(mx0, __shfl_xor_sync(0xffffffffu, mx0, 2));
        mx1 = fmaxf(mx1, __shfl_xor_sync(0xffffffffu, mx1, 1));
        mx1 = fmaxf(mx1, __shfl_xor_sync(0xffffffffu, mx1, 2));

        float mn0 = fmaxf(m0, mx0), mn1 = fmaxf(m1, mx1);
        float sc0 = __expf(m0 - mn0), sc1 = __expf(m1 - mn1);
        m0 = mn0; m1 = mn1;

        float rs0 = 0.f, rs1 = 0.f;
#pragma unroll
        for (int nf = 0; nf < 8; nf++) {
            float p0 = __expf(sacc[nf][0] - mn0);
            float p1 = __expf(sacc[nf][1] - mn0);
            float p2 = __expf(sacc[nf][2] - mn1);
            float p3 = __expf(sacc[nf][3] - mn1);
            rs0 += p0 + p1; rs1 += p2 + p3;
            *(float2*)&Ps[(band + r    ) * PS_STRIDE + nf * 8 + 2 * cq] = make_float2(p0, p1);
            *(float2*)&Ps[(band + r + 8) * PS_STRIDE + nf * 8 + 2 * cq] = make_float2(p2, p3);
        }
        rs0 += __shfl_xor_sync(0xffffffffu, rs0, 1);
        rs0 += __shfl_xor_sync(0xffffffffu, rs0, 2);
        rs1 += __shfl_xor_sync(0xffffffffu, rs1, 1);
        rs1 += __shfl_xor_sync(0xffffffffu, rs1, 2);
        l0 = l0 * sc0 + rs0;
        l1 = l1 * sc1 + rs1;

#pragma unroll
        for (int nf = 0; nf < 16; nf++) {
            oacc[nf][0] *= sc0; oacc[nf][1] *= sc0;
            oacc[nf][2] *= sc1; oacc[nf][3] *= sc1;
        }

        asm volatile("cp.async.wait_group 0;\n");
        __syncthreads();

        if (t + 1 < ntiles) {
            for (int i = tid; i < 2048; i += 256) {
                int rr = i >> 5, c4 = (i & 31) << 2;
                const float* g = Kg + (size_t)((t + 1) * ATT_BK + rr) * KVD + c4;
                uint32_t s = (uint32_t)__cvta_generic_to_shared(&Ks[rr * KS_STRIDE + c4]);
                asm volatile("cp.async.cg.shared.global [%0], [%1], 16;\n" :: "r"(s), "l"(g));
            }
            asm volatile("cp.async.commit_group;\n");
        }

#pragma unroll
        for (int ks = 0; ks < 8; ks++) {
            uint32_t af[4];
            af[0] = Pu[(band + r    ) * PS_STRIDE + ks * 8 + cq    ];
            af[1] = Pu[(band + r + 8) * PS_STRIDE + ks * 8 + cq    ];
            af[2] = Pu[(band + r    ) * PS_STRIDE + ks * 8 + cq + 4];
            af[3] = Pu[(band + r + 8) * PS_STRIDE + ks * 8 + cq + 4];
#pragma unroll
            for (int nf = 0; nf < 16; nf++) {
                uint32_t bf[2];
                bf[0] = Vu[(ks * 8 + cq    ) * VS_STRIDE + nf * 8 + r];
                bf[1] = Vu[(ks * 8 + cq + 4) * VS_STRIDE + nf * 8 + r];
                MMA_TF32(oacc[nf], af, bf);
            }
        }
    }

    float inv0 = 1.f / l0, inv1 = 1.f / l1;
    size_t row0 = (size_t)(q0 + band + r) * DMODEL;
    size_t row1 = (size_t)(q0 + band + r + 8) * DMODEL;
#pragma unroll
    for (int nf = 0; nf < 16; nf++) {
        int col = nf * 8 + 2 * cq;
        *(float2*)&Og[row0 + col] = make_float2(oacc[nf][0] * inv0, oacc[nf][1] * inv0);
        *(float2*)&Og[row1 + col] = make_float2(oacc[nf][2] * inv1, oacc[nf][3] * inv1);
    }
}

// ---------------------------------------------------------------------------
extern "C" void kernel_launch(void* const* d_in, const int* in_sizes, int n_in,
                              void* d_out, int out_size)
{
    const float* x  = (const float*)d_in[0];
    const float* Wq = (const float*)d_in[1];
    const float* Wk = (const float*)d_in[2];
    const float* Wv = (const float*)d_in[3];
    const float* Wo = (const float*)d_in[4];
    const float* qg = (const float*)d_in[5];
    const float* kg = (const float*)d_in[6];
    float* out = (float*)d_out;

    float *pq, *pk, *pv, *po;
    cudaGetSymbolAddress((void**)&pq, g_q);
    cudaGetSymbolAddress((void**)&pk, g_k);
    cudaGetSymbolAddress((void**)&pv, g_v);
    cudaGetSymbolAddress((void**)&po, g_o);

    cudaFuncSetAttribute(tf32gemm,
        cudaFuncAttributeMaxDynamicSharedMemorySize, GEMM_SMEM);
    cudaFuncSetAttribute(tf32gemm_qkv,
        cudaFuncAttributeMaxDynamicSharedMemorySize, GEMM_SMEM);
    cudaFuncSetAttribute(flash_attn_tf32,
        cudaFuncAttributeMaxDynamicSharedMemorySize, ATT_SMEM);

    // Fused Q/K/V projections (TF32 tensor cores, one launch)
    tf32gemm_qkv<<<dim3(24, NTOK / 128), 256, GEMM_SMEM>>>(
        x, Wq, Wk, Wv, pq, pk, pv);

    // Per-head RMSNorm (in place)
    rmsnorm_heads<<<(NTOK * NH  + 7) / 8, 256>>>(pq, qg, NTOK * NH);
    rmsnorm_heads<<<(NTOK * NKV + 7) / 8, 256>>>(pk, kg, NTOK * NKV);

    // Causal GQA attention (TF32 tensor cores)
    flash_attn_tf32<<<dim3(S_LEN / ATT_BQ, NH, NB), 256, ATT_SMEM>>>(pq, pk, pv, po);

    // Output projection + residual (TF32 tensor cores)
    tf32gemm<<<dim3(DMODEL / 128, NTOK / 128), 256, GEMM_SMEM>>>(po, Wo, out, x, DMODEL, DMODEL);
}

// round 10
// speedup vs baseline: 6.1058x; 1.0223x over previous
#include <cuda_runtime.h>
#include <cuda_bf16.h>
#include <cstdint>
#include <cstddef>

// Problem constants
#define S_LEN  2048
#define NB     2
#define NH     16
#define NKV    4
#define DH     128
#define DMODEL 2048   // NH*DH
#define KVD    512    // NKV*DH
#define NTOK   (NB*S_LEN)   // 4096

// Scratch (device globals — no allocations allowed)
__device__ float g_q[(size_t)NTOK * DMODEL];
__device__ float g_k[(size_t)NTOK * KVD];
__device__ float g_v[(size_t)NTOK * KVD];
__device__ float g_o[(size_t)NTOK * DMODEL];

__device__ __forceinline__ uint32_t f2tf32(float x) {
    uint32_t y;
    asm("cvt.rna.tf32.f32 %0, %1;" : "=r"(y) : "f"(x));
    return y;
}

#define MMA_TF32(d, a, b)                                               \
    asm volatile(                                                       \
        "mma.sync.aligned.m16n8k8.row.col.f32.tf32.tf32.f32 "           \
        "{%0,%1,%2,%3}, {%4,%5,%6,%7}, {%8,%9}, {%0,%1,%2,%3};\n"       \
        : "+f"(d[0]), "+f"(d[1]), "+f"(d[2]), "+f"(d[3])                \
        : "r"(a[0]), "r"(a[1]), "r"(a[2]), "r"(a[3]),                   \
          "r"(b[0]), "r"(b[1]))

// ---------------------------------------------------------------------------
// TF32 tensor-core GEMM core: C[M,N] = A[M,K] @ B[K,N] (+ R if R != nullptr)
// BM=128, BN=256, BK=32, 256 threads (8 warps), warp tile 64x64 via m16n8k8.
// MMA operands are raw fp32 bits (HW tf32 truncation) — no CVT in inner loop.
// ---------------------------------------------------------------------------
#define AS_STRIDE 36
#define BS_STRIDE 264
#define ASZ (128 * AS_STRIDE)   // 4608 floats
#define BSZ (32  * BS_STRIDE)   // 8448 floats
#define GEMM_SMEM ((2 * (ASZ + BSZ)) * (int)sizeof(float))  // 104448 B

__device__ __forceinline__ void gemm_core(
    const float* __restrict__ A, const float* __restrict__ B,
    float* __restrict__ C, const float* __restrict__ R,
    int N, int K, int row0, int col0, float* Asm, float* Bsm)
{
    const int tid  = threadIdx.x;
    const int wid  = tid >> 5;
    const int lane = tid & 31;
    const int wm   = wid >> 2;       // 0..1 -> row offset wm*64
    const int wn   = wid & 3;        // 0..3 -> col offset wn*64
    const int r    = lane >> 2;
    const int cq   = lane & 3;

    float acc[4][8][4];
#pragma unroll
    for (int mf = 0; mf < 4; mf++)
#pragma unroll
        for (int nf = 0; nf < 8; nf++)
#pragma unroll
            for (int i = 0; i < 4; i++) acc[mf][nf][i] = 0.f;

    auto cp_tile = [&](int kt, int bufi) {
        float* as = Asm + bufi * ASZ;
        float* bs = Bsm + bufi * BSZ;
        // A: 128 rows x 32 k = 1024 float4 (4/thread)
#pragma unroll
        for (int i = 0; i < 4; i++) {
            int idx = tid + i * 256;
            int ar = idx >> 3, ac = (idx & 7) << 2;
            const float* ga = A + (size_t)(row0 + ar) * K + kt + ac;
            uint32_t sa = (uint32_t)__cvta_generic_to_shared(&as[ar * AS_STRIDE + ac]);
            asm volatile("cp.async.cg.shared.global [%0], [%1], 16;\n"
                         :: "r"(sa), "l"(ga));
        }
        // B: 32 k-rows x 256 cols = 2048 float4 (8/thread)
#pragma unroll
        for (int i = 0; i < 8; i++) {
            int idx = tid + i * 256;
            int br = idx >> 6, bc = (idx & 63) << 2;
            const float* gb = B + (size_t)(kt + br) * N + col0 + bc;
            uint32_t sb = (uint32_t)__cvta_generic_to_shared(&bs[br * BS_STRIDE + bc]);
            asm volatile("cp.async.cg.shared.global [%0], [%1], 16;\n"
                         :: "r"(sb), "l"(gb));
        }
    };

    const int nk = K / 32;
    cp_tile(0, 0);
    asm volatile("cp.async.commit_group;\n");

    int buf = 0;
    for (int t = 0; t < nk; t++) {
        if (t + 1 < nk) cp_tile((t + 1) * 32, buf ^ 1);
        asm volatile("cp.async.commit_group;\n");
        asm volatile("cp.async.wait_group 1;\n");
        __syncthreads();

        const uint32_t* as = (const uint32_t*)(Asm + buf * ASZ);
        const uint32_t* bs = (const uint32_t*)(Bsm + buf * BSZ);
#pragma unroll
        for (int kk = 0; kk < 32; kk += 8) {
            uint32_t af[4][4], bf[8][2];
#pragma unroll
            for (int mf = 0; mf < 4; mf++) {
                int bm = wm * 64 + mf * 16 + r;
                af[mf][0] = as[(bm    ) * AS_STRIDE + kk + cq    ];
                af[mf][1] = as[(bm + 8) * AS_STRIDE + kk + cq    ];
                af[mf][2] = as[(bm    ) * AS_STRIDE + kk + cq + 4];
                af[mf][3] = as[(bm + 8) * AS_STRIDE + kk + cq + 4];
            }
#pragma unroll
            for (int nf = 0; nf < 8; nf++) {
                int bn = wn * 64 + nf * 8 + r;
                bf[nf][0] = bs[(kk + cq    ) * BS_STRIDE + bn];
                bf[nf][1] = bs[(kk + cq + 4) * BS_STRIDE + bn];
            }
#pragma unroll
            for (int mf = 0; mf < 4; mf++)
#pragma unroll
                for (int nf = 0; nf < 8; nf++)
                    MMA_TF32(acc[mf][nf], af[mf], bf[nf]);
        }
        __syncthreads();
        buf ^= 1;
    }

#pragma unroll
    for (int mf = 0; mf < 4; mf++) {
#pragma unroll
        for (int nf = 0; nf < 8; nf++) {
            int row = row0 + wm * 64 + mf * 16 + r;
            int col = col0 + wn * 64 + nf * 8 + cq * 2;
            float2 v0 = make_float2(acc[mf][nf][0], acc[mf][nf][1]);
            float2 v1 = make_float2(acc[mf][nf][2], acc[mf][nf][3]);
            if (R) {
                float2 r0 = *(const float2*)&R[(size_t)row * N + col];
                float2 r1 = *(const float2*)&R[(size_t)(row + 8) * N + col];
                v0.x += r0.x; v0.y += r0.y;
                v1.x += r1.x; v1.y += r1.y;
            }
            *(float2*)&C[(size_t)row * N + col]       = v0;
            *(float2*)&C[(size_t)(row + 8) * N + col] = v1;
        }
    }
}

// Generic single-matrix GEMM (used for Wo + residual)
__global__ __launch_bounds__(256) void tf32gemm(
    const float* __restrict__ A, const float* __restrict__ B,
    float* __restrict__ C, const float* __restrict__ R,
    int N, int K)
{
    extern __shared__ float sm[];
    gemm_core(A, B, C, R, N, K, blockIdx.y * 128, blockIdx.x * 256,
              sm, sm + 2 * ASZ);
}

// Fused QKV: blockIdx.x 0..7 -> Wq cols, 8..9 -> Wk, 10..11 -> Wv.
__global__ __launch_bounds__(256) void tf32gemm_qkv(
    const float* __restrict__ A,
    const float* __restrict__ Wq, const float* __restrict__ Wk,
    const float* __restrict__ Wv,
    float* __restrict__ Cq, float* __restrict__ Ck, float* __restrict__ Cv)
{
    extern __shared__ float sm[];
    const int bx = blockIdx.x;
    const float* B;
    float* C;
    int N, col0;
    if (bx < 8)       { B = Wq; C = Cq; N = DMODEL; col0 = bx * 256; }
    else if (bx < 10) { B = Wk; C = Ck; N = KVD;    col0 = (bx - 8) * 256; }
    else              { B = Wv; C = Cv; N = KVD;    col0 = (bx - 10) * 256; }
    gemm_core(A, B, C, nullptr, N, DMODEL, blockIdx.y * 128, col0,
              sm, sm + 2 * ASZ);
}

// ---------------------------------------------------------------------------
// Per-head RMSNorm over DH=128, in-place. One warp per head-row.
// ---------------------------------------------------------------------------
__global__ __launch_bounds__(256) void rmsnorm_heads(
    float* __restrict__ t, const float* __restrict__ gamma, int nrows)
{
    int row  = blockIdx.x * 8 + (threadIdx.x >> 5);
    if (row >= nrows) return;
    int lane = threadIdx.x & 31;

    float4 v = *(float4*)&t[(size_t)row * DH + lane * 4];
    float ss = v.x * v.x + v.y * v.y + v.z * v.z + v.w * v.w;
#pragma unroll
    for (int m = 16; m; m >>= 1) ss += __shfl_xor_sync(0xffffffffu, ss, m);
    float r = rsqrtf(ss * (1.0f / DH) + 1e-8f);

    float4 g = *(const float4*)&gamma[lane * 4];
    v.x *= r * g.x; v.y *= r * g.y; v.z *= r * g.z; v.w *= r * g.w;
    *(float4*)&t[(size_t)row * DH + lane * 4] = v;
}

// ---------------------------------------------------------------------------
// TF32 mma.sync causal flash attention (R8 structure, heavy-CTA-first).
// ---------------------------------------------------------------------------
#define ATT_BQ   128
#define ATT_BK   64
#define KS_STRIDE 132
#define VS_STRIDE 136
#define PS_STRIDE 68
#define ATT_SMEM ((64 * KS_STRIDE + 64 * VS_STRIDE + 128 * PS_STRIDE) * (int)sizeof(float))

__global__ __launch_bounds__(256) void flash_attn_tf32(
    const float* __restrict__ Q, const float* __restrict__ K,
    const float* __restrict__ V, float* __restrict__ O)
{
    extern __shared__ float sm[];
    float* Ks = sm;
    float* Vs = Ks + 64 * KS_STRIDE;
    float* Ps = Vs + 64 * VS_STRIDE;

    const int bq  = gridDim.x - 1 - blockIdx.x;
    const int h   = blockIdx.y;
    const int b   = blockIdx.z;
    const int kvh = h >> 2;

    const int tid  = threadIdx.x;
    const int wid  = tid >> 5;
    const int lane = tid & 31;
    const int r    = lane >> 2;
    const int cq   = lane & 3;
    const int band = wid * 16;

    const float* Qg = Q + (size_t)b * S_LEN * DMODEL + h * DH;
    const float* Kg = K + (size_t)b * S_LEN * KVD + kvh * DH;
    const float* Vg = V + (size_t)b * S_LEN * KVD + kvh * DH;
    float*       Og = O + (size_t)b * S_LEN * DMODEL + h * DH;

    const int q0 = bq * ATT_BQ;
    const float qscale = 0.08838834764831845f;

    {
#pragma unroll
        for (int i = tid; i < 2048; i += 256) {
            int rr = i >> 5, c4 = (i & 31) << 2;
            const float* g = Kg + (size_t)rr * KVD + c4;
            uint32_t s = (uint32_t)__cvta_generic_to_shared(&Ks[rr * KS_STRIDE + c4]);
            asm volatile("cp.async.cg.shared.global [%0], [%1], 16;\n" :: "r"(s), "l"(g));
        }
        asm volatile("cp.async.commit_group;\n");
    }

    uint32_t qf[16][4];
#pragma unroll
    for (int chunk = 0; chunk < 2; chunk++) {
        __syncthreads();
        for (int i = tid; i < 2048; i += 256) {
            int rr = i >> 5, c4 = (i & 31) << 2;
            float4 v = *(const float4*)&Qg[(size_t)(q0 + chunk * 64 + rr) * DMODEL + c4];
            v.x *= qscale; v.y *= qscale; v.z *= qscale; v.w *= qscale;
            *(float4*)&Vs[rr * KS_STRIDE + c4] = v;
        }
        __syncthreads();
        if ((wid >> 2) == chunk) {
            int lr = (wid & 3) * 16;
#pragma unroll
            for (int ks = 0; ks < 16; ks++) {
                qf[ks][0] = f2tf32(Vs[(lr + r    ) * KS_STRIDE + ks * 8 + cq    ]);
                qf[ks][1] = f2tf32(Vs[(lr + r + 8) * KS_STRIDE + ks * 8 + cq    ]);
                qf[ks][2] = f2tf32(Vs[(lr + r    ) * KS_STRIDE + ks * 8 + cq + 4]);
                qf[ks][3] = f2tf32(Vs[(lr + r + 8) * KS_STRIDE + ks * 8 + cq + 4]);
            }
        }
    }

    float oacc[16][4];
#pragma unroll
    for (int nf = 0; nf < 16; nf++)
#pragma unroll
        for (int j = 0; j < 4; j++) oacc[nf][j] = 0.f;
    float m0 = -1e30f, m1 = -1e30f, l0 = 0.f, l1 = 0.f;

    const uint32_t* Ku = (const uint32_t*)Ks;
    const uint32_t* Vu = (const uint32_t*)Vs;
    const uint32_t* Pu = (const uint32_t*)Ps;

    const int ntiles = 2 * bq + 2;
    for (int t = 0; t < ntiles; t++) {
        asm volatile("cp.async.wait_group 0;\n");
        __syncthreads();

        for (int i = tid; i < 2048; i += 256) {
            int rr = i >> 5, c4 = (i & 31) << 2;
            const float* g = Vg + (size_t)(t * ATT_BK + rr) * KVD + c4;
            uint32_t s = (uint32_t)__cvta_generic_to_shared(&Vs[rr * VS_STRIDE + c4]);
            asm volatile("cp.async.cg.shared.global [%0], [%1], 16;\n" :: "r"(s), "l"(g));
        }
        asm volatile("cp.async.commit_group;\n");

        float sacc[8][4];
#pragma unroll
        for (int nf = 0; nf < 8; nf++)
#pragma unroll
            for (int j = 0; j < 4; j++) sacc[nf][j] = 0.f;

#pragma unroll
        for (int ks = 0; ks < 16; ks++) {
#pragma unroll
            for (int nf = 0; nf < 8; nf++) {
                uint32_t bf[2];
                bf[0] = Ku[(nf * 8 + r) * KS_STRIDE + ks * 8 + cq    ];
                bf[1] = Ku[(nf * 8 + r) * KS_STRIDE + ks * 8 + cq + 4];
                MMA_TF32(sacc[nf], qf[ks], bf);
            }
        }

        if (t >= 2 * bq) {
            int gq0 = q0 + band + r;
            int gq1 = gq0 + 8;
#pragma unroll
            for (int nf = 0; nf < 8; nf++) {
                int gk = t * ATT_BK + nf * 8 + 2 * cq;
                if (gk     > gq0) sacc[nf][0] = -1e30f;
                if (gk + 1 > gq0) sacc[nf][1] = -1e30f;
                if (gk     > gq1) sacc[nf][2] = -1e30f;
                if (gk + 1 > gq1) sacc[nf][3] = -1e30f;
            }
        }

        float mx0 = -1e30f, mx1 = -1e30f;
#pragma unroll
        for (int nf = 0; nf < 8; nf++) {
            mx0 = fmaxf(mx0, fmaxf(sacc[nf][0], sacc[nf][1]));
            mx1 = fmaxf(mx1, fmaxf(sacc[nf][2], sacc[nf][3]));
        }
        mx0 = fmaxf(mx0, __shfl_xor_sync(0xffffffffu, mx0, 1));
        mx0 = fmaxf(mx0, __shfl_xor_sync(0xffffffffu, mx0, 2));
        mx1 = fmaxf(mx1, __shfl_xor_sync(0xffffffffu, mx1, 1));
        mx1 = fmaxf(mx1, __shfl_xor_sync(0xffffffffu, mx1, 2));

        float mn0 = fmaxf(m0, mx0), mn1 = fmaxf(m1, mx1);
        float sc0 = __expf(m0 - mn0), sc1 = __expf(m1 - mn1);
        m0 = mn0; m1 = mn1;

        float rs0 = 0.f, rs1 = 0.f;
#pragma unroll
        for (int nf = 0; nf < 8; nf++) {
            float p0 = __expf(sacc[nf][0] - mn0);
            float p1 = __expf(sacc[nf][1] - mn0);
            float p2 = __expf(sacc[nf][2] - mn1);
            float p3 = __expf(sacc[nf][3] - mn1);
            rs0 += p0 + p1; rs1 += p2 + p3;
            *(float2*)&Ps[(band + r    ) * PS_STRIDE + nf * 8 + 2 * cq] = make_float2(p0, p1);
            *(float2*)&Ps[(band + r + 8) * PS_STRIDE + nf * 8 + 2 * cq] = make_float2(p2, p3);
        }
        rs0 += __shfl_xor_sync(0xffffffffu, rs0, 1);
        rs0 += __shfl_xor_sync(0xffffffffu, rs0, 2);
        rs1 += __shfl_xor_sync(0xffffffffu, rs1, 1);
        rs1 += __shfl_xor_sync(0xffffffffu, rs1, 2);
        l0 = l0 * sc0 + rs0;
        l1 = l1 * sc1 + rs1;

#pragma unroll
        for (int nf = 0; nf < 16; nf++) {
            oacc[nf][0] *= sc0; oacc[nf][1] *= sc0;
            oacc[nf][2] *= sc1; oacc[nf][3] *= sc1;
        }

        asm volatile("cp.async.wait_group 0;\n");
        __syncthreads();

        if (t + 1 < ntiles) {
            for (int i = tid; i < 2048; i += 256) {
                int rr = i >> 5, c4 = (i & 31) << 2;
                const float* g = Kg + (size_t)((t + 1) * ATT_BK + rr) * KVD + c4;
                uint32_t s = (uint32_t)__cvta_generic_to_shared(&Ks[rr * KS_STRIDE + c4]);
                asm volatile("cp.async.cg.shared.global [%0], [%1], 16;\n" :: "r"(s), "l"(g));
            }
            asm volatile("cp.async.commit_group;\n");
        }

#pragma unroll
        for (int ks = 0; ks < 8; ks++) {
            uint32_t af[4];
            af[0] = Pu[(band + r    ) * PS_STRIDE + ks * 8 + cq    ];
            af[1] = Pu[(band + r + 8) * PS_STRIDE + ks * 8 + cq    ];
            af[2] = Pu[(band + r    ) * PS_STRIDE + ks * 8 + cq + 4];
            af[3] = Pu[(band + r + 8) * PS_STRIDE + ks * 8 + cq + 4];
#pragma unroll
            for (int nf = 0; nf < 16; nf++) {
                uint32_t bf[2];
                bf[0] = Vu[(ks * 8 + cq    ) * VS_STRIDE + nf * 8 + r];
                bf[1] = Vu[(ks * 8 + cq + 4) * VS_STRIDE + nf * 8 + r];
                MMA_TF32(oacc[nf], af, bf);
            }
        }
    }

    float inv0 = 1.f / l0, inv1 = 1.f / l1;
    size_t row0 = (size_t)(q0 + band + r) * DMODEL;
    size_t row1 = (size_t)(q0 + band + r + 8) * DMODEL;
#pragma unroll
    for (int nf = 0; nf < 16; nf++) {
        int col = nf * 8 + 2 * cq;
        *(float2*)&Og[row0 + col] = make_float2(oacc[nf][0] * inv0, oacc[nf][1] * inv0);
        *(float2*)&Og[row1 + col] = make_float2(oacc[nf][2] * inv1, oacc[nf][3] * inv1);
    }
}

// ---------------------------------------------------------------------------
extern "C" void kernel_launch(void* const* d_in, const int* in_sizes, int n_in,
                              void* d_out, int out_size)
{
    const float* x  = (const float*)d_in[0];
    const float* Wq = (const float*)d_in[1];
    const float* Wk = (const float*)d_in[2];
    const float* Wv = (const float*)d_in[3];
    const float* Wo = (const float*)d_in[4];
    const float* qg = (const float*)d_in[5];
    const float* kg = (const float*)d_in[6];
    float* out = (float*)d_out;

    float *pq, *pk, *pv, *po;
    cudaGetSymbolAddress((void**)&pq, g_q);
    cudaGetSymbolAddress((void**)&pk, g_k);
    cudaGetSymbolAddress((void**)&pv, g_v);
    cudaGetSymbolAddress((void**)&po, g_o);

    cudaFuncSetAttribute(tf32gemm,
        cudaFuncAttributeMaxDynamicSharedMemorySize, GEMM_SMEM);
    cudaFuncSetAttribute(tf32gemm_qkv,
        cudaFuncAttributeMaxDynamicSharedMemorySize, GEMM_SMEM);
    cudaFuncSetAttribute(flash_attn_tf32,
        cudaFuncAttributeMaxDynamicSharedMemorySize, ATT_SMEM);

    // Fused Q/K/V projections (TF32 tensor cores, one launch, BN=256 tiles)
    tf32gemm_qkv<<<dim3(12, NTOK / 128), 256, GEMM_SMEM>>>(
        x, Wq, Wk, Wv, pq, pk, pv);

    // Per-head RMSNorm (in place)
    rmsnorm_heads<<<(NTOK * NH  + 7) / 8, 256>>>(pq, qg, NTOK * NH);
    rmsnorm_heads<<<(NTOK * NKV + 7) / 8, 256>>>(pk, kg, NTOK * NKV);

    // Causal GQA attention (TF32 tensor cores)
    flash_attn_tf32<<<dim3(S_LEN / ATT_BQ, NH, NB), 256, ATT_SMEM>>>(pq, pk, pv, po);

    // Output projection + residual (TF32 tensor cores)
    tf32gemm<<<dim3(DMODEL / 256, NTOK / 128), 256, GEMM_SMEM>>>(po, Wo, out, x, DMODEL, DMODEL);
}

// round 13
// speedup vs baseline: 6.6239x; 1.0849x over previous
#include <cuda_runtime.h>
#include <cuda_bf16.h>
#include <cstdint>
#include <cstddef>

// Problem constants
#define S_LEN  2048
#define NB     2
#define NH     16
#define NKV    4
#define DH     128
#define DMODEL 2048   // NH*DH
#define KVD    512    // NKV*DH
#define NTOK   (NB*S_LEN)   // 4096

// Scratch (device globals — no allocations allowed)
__device__ float g_q[(size_t)NTOK * DMODEL];
__device__ float g_k[(size_t)NTOK * KVD];
__device__ float g_v[(size_t)NTOK * KVD];
__device__ float g_o[(size_t)NTOK * DMODEL];
__device__ __nv_bfloat16 g_qh[(size_t)NTOK * DMODEL];  // normalized Q, bf16, qscale folded
__device__ __nv_bfloat16 g_kh[(size_t)NTOK * KVD];     // normalized K, bf16

#define MMA_TF32(d, a, b)                                               \
    asm volatile(                                                       \
        "mma.sync.aligned.m16n8k8.row.col.f32.tf32.tf32.f32 "           \
        "{%0,%1,%2,%3}, {%4,%5,%6,%7}, {%8,%9}, {%0,%1,%2,%3};\n"       \
        : "+f"(d[0]), "+f"(d[1]), "+f"(d[2]), "+f"(d[3])                \
        : "r"(a[0]), "r"(a[1]), "r"(a[2]), "r"(a[3]),                   \
          "r"(b[0]), "r"(b[1]))

#define MMA_BF16(d, a, b)                                               \
    asm volatile(                                                       \
        "mma.sync.aligned.m16n8k16.row.col.f32.bf16.bf16.f32 "          \
        "{%0,%1,%2,%3}, {%4,%5,%6,%7}, {%8,%9}, {%0,%1,%2,%3};\n"       \
        : "+f"(d[0]), "+f"(d[1]), "+f"(d[2]), "+f"(d[3])                \
        : "r"(a[0]), "r"(a[1]), "r"(a[2]), "r"(a[3]),                   \
          "r"(b[0]), "r"(b[1]))

// ---------------------------------------------------------------------------
// TF32 tensor-core GEMM core (unchanged from R10 — passing config).
// BM=128, BN=256, BK=32, 256 threads (8 warps), warp tile 64x64 via m16n8k8.
// ---------------------------------------------------------------------------
#define AS_STRIDE 36
#define BS_STRIDE 264
#define ASZ (128 * AS_STRIDE)
#define BSZ (32  * BS_STRIDE)
#define GEMM_SMEM ((2 * (ASZ + BSZ)) * (int)sizeof(float))  // 104448 B

__device__ __forceinline__ void gemm_core(
    const float* __restrict__ A, const float* __restrict__ B,
    float* __restrict__ C, const float* __restrict__ R,
    int N, int K, int row0, int col0, float* Asm, float* Bsm)
{
    const int tid  = threadIdx.x;
    const int wid  = tid >> 5;
    const int lane = tid & 31;
    const int wm   = wid >> 2;
    const int wn   = wid & 3;
    const int r    = lane >> 2;
    const int cq   = lane & 3;

    float acc[4][8][4];
#pragma unroll
    for (int mf = 0; mf < 4; mf++)
#pragma unroll
        for (int nf = 0; nf < 8; nf++)
#pragma unroll
            for (int i = 0; i < 4; i++) acc[mf][nf][i] = 0.f;

    auto cp_tile = [&](int kt, int bufi) {
        float* as = Asm + bufi * ASZ;
        float* bs = Bsm + bufi * BSZ;
#pragma unroll
        for (int i = 0; i < 4; i++) {
            int idx = tid + i * 256;
            int ar = idx >> 3, ac = (idx & 7) << 2;
            const float* ga = A + (size_t)(row0 + ar) * K + kt + ac;
            uint32_t sa = (uint32_t)__cvta_generic_to_shared(&as[ar * AS_STRIDE + ac]);
            asm volatile("cp.async.cg.shared.global [%0], [%1], 16;\n"
                         :: "r"(sa), "l"(ga));
        }
#pragma unroll
        for (int i = 0; i < 8; i++) {
            int idx = tid + i * 256;
            int br = idx >> 6, bc = (idx & 63) << 2;
            const float* gb = B + (size_t)(kt + br) * N + col0 + bc;
            uint32_t sb = (uint32_t)__cvta_generic_to_shared(&bs[br * BS_STRIDE + bc]);
            asm volatile("cp.async.cg.shared.global [%0], [%1], 16;\n"
                         :: "r"(sb), "l"(gb));
        }
    };

    const int nk = K / 32;
    cp_tile(0, 0);
    asm volatile("cp.async.commit_group;\n");

    int buf = 0;
    for (int t = 0; t < nk; t++) {
        if (t + 1 < nk) cp_tile((t + 1) * 32, buf ^ 1);
        asm volatile("cp.async.commit_group;\n");
        asm volatile("cp.async.wait_group 1;\n");
        __syncthreads();

        const uint32_t* as = (const uint32_t*)(Asm + buf * ASZ);
        const uint32_t* bs = (const uint32_t*)(Bsm + buf * BSZ);
#pragma unroll
        for (int kk = 0; kk < 32; kk += 8) {
            uint32_t af[4][4], bf[8][2];
#pragma unroll
            for (int mf = 0; mf < 4; mf++) {
                int bm = wm * 64 + mf * 16 + r;
                af[mf][0] = as[(bm    ) * AS_STRIDE + kk + cq    ];
                af[mf][1] = as[(bm + 8) * AS_STRIDE + kk + cq    ];
                af[mf][2] = as[(bm    ) * AS_STRIDE + kk + cq + 4];
                af[mf][3] = as[(bm + 8) * AS_STRIDE + kk + cq + 4];
            }
#pragma unroll
            for (int nf = 0; nf < 8; nf++) {
                int bn = wn * 64 + nf * 8 + r;
                bf[nf][0] = bs[(kk + cq    ) * BS_STRIDE + bn];
                bf[nf][1] = bs[(kk + cq + 4) * BS_STRIDE + bn];
            }
#pragma unroll
            for (int mf = 0; mf < 4; mf++)
#pragma unroll
                for (int nf = 0; nf < 8; nf++)
                    MMA_TF32(acc[mf][nf], af[mf], bf[nf]);
        }
        __syncthreads();
        buf ^= 1;
    }

#pragma unroll
    for (int mf = 0; mf < 4; mf++) {
#pragma unroll
        for (int nf = 0; nf < 8; nf++) {
            int row = row0 + wm * 64 + mf * 16 + r;
            int col = col0 + wn * 64 + nf * 8 + cq * 2;
            float2 v0 = make_float2(acc[mf][nf][0], acc[mf][nf][1]);
            float2 v1 = make_float2(acc[mf][nf][2], acc[mf][nf][3]);
            if (R) {
                float2 r0 = *(const float2*)&R[(size_t)row * N + col];
                float2 r1 = *(const float2*)&R[(size_t)(row + 8) * N + col];
                v0.x += r0.x; v0.y += r0.y;
                v1.x += r1.x; v1.y += r1.y;
            }
            *(float2*)&C[(size_t)row * N + col]       = v0;
            *(float2*)&C[(size_t)(row + 8) * N + col] = v1;
        }
    }
}

__global__ __launch_bounds__(256) void tf32gemm(
    const float* __restrict__ A, const float* __restrict__ B,
    float* __restrict__ C, const float* __restrict__ R,
    int N, int K)
{
    extern __shared__ float sm[];
    gemm_core(A, B, C, R, N, K, blockIdx.y * 128, blockIdx.x * 256,
              sm, sm + 2 * ASZ);
}

__global__ __launch_bounds__(256) void tf32gemm_qkv(
    const float* __restrict__ A,
    const float* __restrict__ Wq, const float* __restrict__ Wk,
    const float* __restrict__ Wv,
    float* __restrict__ Cq, float* __restrict__ Ck, float* __restrict__ Cv)
{
    extern __shared__ float sm[];
    const int bx = blockIdx.x;
    const float* B;
    float* C;
    int N, col0;
    if (bx < 8)       { B = Wq; C = Cq; N = DMODEL; col0 = bx * 256; }
    else if (bx < 10) { B = Wk; C = Ck; N = KVD;    col0 = (bx - 8) * 256; }
    else              { B = Wv; C = Cv; N = KVD;    col0 = (bx - 10) * 256; }
    gemm_core(A, B, C, nullptr, N, DMODEL, blockIdx.y * 128, col0,
              sm, sm + 2 * ASZ);
}

// ---------------------------------------------------------------------------
// Per-head RMSNorm over DH=128 -> bf16 output (scale folded). One warp/row.
// ---------------------------------------------------------------------------
__global__ __launch_bounds__(256) void rmsnorm_to_bf16(
    const float* __restrict__ t, const float* __restrict__ gamma,
    __nv_bfloat16* __restrict__ out, int nrows, float scale)
{
    int row  = blockIdx.x * 8 + (threadIdx.x >> 5);
    if (row >= nrows) return;
    int lane = threadIdx.x & 31;

    float4 v = *(const float4*)&t[(size_t)row * DH + lane * 4];
    float ss = v.x * v.x + v.y * v.y + v.z * v.z + v.w * v.w;
#pragma unroll
    for (int m = 16; m; m >>= 1) ss += __shfl_xor_sync(0xffffffffu, ss, m);
    float r = rsqrtf(ss * (1.0f / DH) + 1e-8f) * scale;

    float4 g = *(const float4*)&gamma[lane * 4];
    __nv_bfloat162 p0 = __floats2bfloat162_rn(v.x * r * g.x, v.y * r * g.y);
    __nv_bfloat162 p1 = __floats2bfloat162_rn(v.z * r * g.z, v.w * r * g.w);
    uint2 packed = make_uint2(*(uint32_t*)&p0, *(uint32_t*)&p1);
    *(uint2*)&out[(size_t)row * DH + lane * 4] = packed;
}

// ---------------------------------------------------------------------------
// Causal flash attention: QK^T in bf16 (m16n8k16), PV in tf32 (m16n8k8).
// BQ=128, BK=64, 8 warps, warp = 16 q-rows. Q/K bf16 (pre-normalized,
// qscale folded). Heavy-CTA-first scheduling.
// smem (words): Ks 64x68 (bf16 pairs), Vs 64x136 (fp32), Ps 128x68 (fp32).
// ---------------------------------------------------------------------------
#define ATT_BQ   128
#define ATT_BK   64
#define KSW 68     // K row stride in 32-bit words (136 halves = 272 B)
#define VS_STRIDE 136
#define PS_STRIDE 68
#define ATT_SMEM ((64 * KSW + 64 * VS_STRIDE + 128 * PS_STRIDE) * (int)sizeof(uint32_t)) // 87040

__global__ __launch_bounds__(256) void flash_attn_mixed(
    const __nv_bfloat16* __restrict__ Qh, const __nv_bfloat16* __restrict__ Kh,
    const float* __restrict__ V, float* __restrict__ O)
{
    extern __shared__ float sm[];
    uint32_t* Kw = (uint32_t*)sm;                    // 64*68 words (bf16x2)
    float*    Vs = sm + 64 * KSW;                    // 64*136 fp32 (also Q staging)
    float*    Ps = Vs + 64 * VS_STRIDE;              // 128*68 fp32

    const int bq  = gridDim.x - 1 - blockIdx.x;      // heavy CTAs first
    const int h   = blockIdx.y;
    const int b   = blockIdx.z;
    const int kvh = h >> 2;

    const int tid  = threadIdx.x;
    const int wid  = tid >> 5;
    const int lane = tid & 31;
    const int r    = lane >> 2;
    const int cq   = lane & 3;
    const int band = wid * 16;

    const __nv_bfloat16* Qg = Qh + (size_t)b * S_LEN * DMODEL + h * DH;
    const __nv_bfloat16* Kg = Kh + (size_t)b * S_LEN * KVD + kvh * DH;
    const float*         Vg = V  + (size_t)b * S_LEN * KVD + kvh * DH;
    float*               Og = O  + (size_t)b * S_LEN * DMODEL + h * DH;

    const int q0 = bq * ATT_BQ;

    // Prefetch K tile 0 (bf16: 64 rows x 16 x 16B chunks)
    {
#pragma unroll
        for (int i = tid; i < 1024; i += 256) {
            int rr = i >> 4, ch = i & 15;
            const __nv_bfloat16* g = Kg + (size_t)rr * KVD + ch * 8;
            uint32_t s = (uint32_t)__cvta_generic_to_shared(&Kw[rr * KSW + ch * 4]);
            asm volatile("cp.async.cg.shared.global [%0], [%1], 16;\n" :: "r"(s), "l"(g));
        }
        asm volatile("cp.async.commit_group;\n");
    }
    // Stage all 128 Q rows (bf16) into the V buffer (fits exactly)
    {
        uint32_t* Qstage = (uint32_t*)Vs;
#pragma unroll
        for (int i = tid; i < 2048; i += 256) {
            int rr = i >> 4, ch = i & 15;
            const __nv_bfloat16* g = Qg + (size_t)(q0 + rr) * DMODEL + ch * 8;
            uint32_t s = (uint32_t)__cvta_generic_to_shared(&Qstage[rr * KSW + ch * 4]);
            asm volatile("cp.async.cg.shared.global [%0], [%1], 16;\n" :: "r"(s), "l"(g));
        }
        asm volatile("cp.async.commit_group;\n");
    }
    asm volatile("cp.async.wait_group 0;\n");
    __syncthreads();

    // Extract Q fragments (bf16x2, m16n8k16 A layout): 8 k-steps x 4 regs
    uint32_t qf[8][4];
    {
        const uint32_t* Qstage = (const uint32_t*)Vs;
#pragma unroll
        for (int ks = 0; ks < 8; ks++) {
            qf[ks][0] = Qstage[(band + r    ) * KSW + ks * 8 + cq    ];
            qf[ks][1] = Qstage[(band + r + 8) * KSW + ks * 8 + cq    ];
            qf[ks][2] = Qstage[(band + r    ) * KSW + ks * 8 + cq + 4];
            qf[ks][3] = Qstage[(band + r + 8) * KSW + ks * 8 + cq + 4];
        }
    }

    float oacc[16][4];
#pragma unroll
    for (int nf = 0; nf < 16; nf++)
#pragma unroll
        for (int j = 0; j < 4; j++) oacc[nf][j] = 0.f;
    float m0 = -1e30f, m1 = -1e30f, l0 = 0.f, l1 = 0.f;

    const uint32_t* Vu = (const uint32_t*)Vs;
    const uint32_t* Pu = (const uint32_t*)Ps;

    const int ntiles = 2 * bq + 2;
    for (int t = 0; t < ntiles; t++) {
        asm volatile("cp.async.wait_group 0;\n");
        __syncthreads();   // K_t resident; prev PV done with Vs/Ps; qf extracted

        // Prefetch V_t (fp32) — overlaps QK^T
        for (int i = tid; i < 2048; i += 256) {
            int rr = i >> 5, c4 = (i & 31) << 2;
            const float* g = Vg + (size_t)(t * ATT_BK + rr) * KVD + c4;
            uint32_t s = (uint32_t)__cvta_generic_to_shared(&Vs[rr * VS_STRIDE + c4]);
            asm volatile("cp.async.cg.shared.global [%0], [%1], 16;\n" :: "r"(s), "l"(g));
        }
        asm volatile("cp.async.commit_group;\n");

        // S = Q K^T  (bf16 m16n8k16: 8 k-steps x 8 col-frags)
        float sacc[8][4];
#pragma unroll
        for (int nf = 0; nf < 8; nf++)
#pragma unroll
            for (int j = 0; j < 4; j++) sacc[nf][j] = 0.f;

#pragma unroll
        for (int ks = 0; ks < 8; ks++) {
#pragma unroll
            for (int nf = 0; nf < 8; nf++) {
                uint32_t bf[2];
                bf[0] = Kw[(nf * 8 + r) * KSW + ks * 8 + cq    ];
                bf[1] = Kw[(nf * 8 + r) * KSW + ks * 8 + cq + 4];
                MMA_BF16(sacc[nf], qf[ks], bf);
            }
        }

        // Causal mask (last two tiles)
        if (t >= 2 * bq) {
            int gq0 = q0 + band + r;
            int gq1 = gq0 + 8;
#pragma unroll
            for (int nf = 0; nf < 8; nf++) {
                int gk = t * ATT_BK + nf * 8 + 2 * cq;
                if (gk     > gq0) sacc[nf][0] = -1e30f;
                if (gk + 1 > gq0) sacc[nf][1] = -1e30f;
                if (gk     > gq1) sacc[nf][2] = -1e30f;
                if (gk + 1 > gq1) sacc[nf][3] = -1e30f;
            }
        }

        // Online softmax (warp-local row reductions over lanes 1,2)
        float mx0 = -1e30f, mx1 = -1e30f;
#pragma unroll
        for (int nf = 0; nf < 8; nf++) {
            mx0 = fmaxf(mx0, fmaxf(sacc[nf][0], sacc[nf][1]));
            mx1 = fmaxf(mx1, fmaxf(sacc[nf][2], sacc[nf][3]));
        }
        mx0 = fmaxf(mx0, __shfl_xor_sync(0xffffffffu, mx0, 1));
        mx0 = fmaxf(mx0, __shfl_xor_sync(0xffffffffu, mx0, 2));
        mx1 = fmaxf(mx1, __shfl_xor_sync(0xffffffffu, mx1, 1));
        mx1 = fmaxf(mx1, __shfl_xor_sync(0xffffffffu, mx1, 2));

        float mn0 = fmaxf(m0, mx0), mn1 = fmaxf(m1, mx1);
        float sc0 = __expf(m0 - mn0), sc1 = __expf(m1 - mn1);
        m0 = mn0; m1 = mn1;

        float rs0 = 0.f, rs1 = 0.f;
#pragma unroll
        for (int nf = 0; nf < 8; nf++) {
            float p0 = __expf(sacc[nf][0] - mn0);
            float p1 = __expf(sacc[nf][1] - mn0);
            float p2 = __expf(sacc[nf][2] - mn1);
            float p3 = __expf(sacc[nf][3] - mn1);
            rs0 += p0 + p1; rs1 += p2 + p3;
            *(float2*)&Ps[(band + r    ) * PS_STRIDE + nf * 8 + 2 * cq] = make_float2(p0, p1);
            *(float2*)&Ps[(band + r + 8) * PS_STRIDE + nf * 8 + 2 * cq] = make_float2(p2, p3);
        }
        rs0 += __shfl_xor_sync(0xffffffffu, rs0, 1);
        rs0 += __shfl_xor_sync(0xffffffffu, rs0, 2);
        rs1 += __shfl_xor_sync(0xffffffffu, rs1, 1);
        rs1 += __shfl_xor_sync(0xffffffffu, rs1, 2);
        l0 = l0 * sc0 + rs0;
        l1 = l1 * sc1 + rs1;

#pragma unroll
        for (int nf = 0; nf < 16; nf++) {
            oacc[nf][0] *= sc0; oacc[nf][1] *= sc0;
            oacc[nf][2] *= sc1; oacc[nf][3] *= sc1;
        }

        asm volatile("cp.async.wait_group 0;\n");
        __syncthreads();   // V_t resident; all warps past K reads & P stores

        // Prefetch K_{t+1} (bf16) — overlaps PV
        if (t + 1 < ntiles) {
            for (int i = tid; i < 1024; i += 256) {
                int rr = i >> 4, ch = i & 15;
                const __nv_bfloat16* g = Kg + (size_t)((t + 1) * ATT_BK + rr) * KVD + ch * 8;
                uint32_t s = (uint32_t)__cvta_generic_to_shared(&Kw[rr * KSW + ch * 4]);
                asm volatile("cp.async.cg.shared.global [%0], [%1], 16;\n" :: "r"(s), "l"(g));
            }
            asm volatile("cp.async.commit_group;\n");
        }

        // O += P V (tf32 m16n8k8)
#pragma unroll
        for (int ks = 0; ks < 8; ks++) {
            uint32_t af[4];
            af[0] = Pu[(band + r    ) * PS_STRIDE + ks * 8 + cq    ];
            af[1] = Pu[(band + r + 8) * PS_STRIDE + ks * 8 + cq    ];
            af[2] = Pu[(band + r    ) * PS_STRIDE + ks * 8 + cq + 4];
            af[3] = Pu[(band + r + 8) * PS_STRIDE + ks * 8 + cq + 4];
#pragma unroll
            for (int nf = 0; nf < 16; nf++) {
                uint32_t bf[2];
                bf[0] = Vu[(ks * 8 + cq    ) * VS_STRIDE + nf * 8 + r];
                bf[1] = Vu[(ks * 8 + cq + 4) * VS_STRIDE + nf * 8 + r];
                MMA_TF32(oacc[nf], af, bf);
            }
        }
    }

    float inv0 = 1.f / l0, inv1 = 1.f / l1;
    size_t row0 = (size_t)(q0 + band + r) * DMODEL;
    size_t row1 = (size_t)(q0 + band + r + 8) * DMODEL;
#pragma unroll
    for (int nf = 0; nf < 16; nf++) {
        int col = nf * 8 + 2 * cq;
        *(float2*)&Og[row0 + col] = make_float2(oacc[nf][0] * inv0, oacc[nf][1] * inv0);
        *(float2*)&Og[row1 + col] = make_float2(oacc[nf][2] * inv1, oacc[nf][3] * inv1);
    }
}

// ---------------------------------------------------------------------------
extern "C" void kernel_launch(void* const* d_in, const int* in_sizes, int n_in,
                              void* d_out, int out_size)
{
    const float* x  = (const float*)d_in[0];
    const float* Wq = (const float*)d_in[1];
    const float* Wk = (const float*)d_in[2];
    const float* Wv = (const float*)d_in[3];
    const float* Wo = (const float*)d_in[4];
    const float* qg = (const float*)d_in[5];
    const float* kg = (const float*)d_in[6];
    float* out = (float*)d_out;

    float *pq, *pk, *pv, *po;
    __nv_bfloat16 *pqh, *pkh;
    cudaGetSymbolAddress((void**)&pq,  g_q);
    cudaGetSymbolAddress((void**)&pk,  g_k);
    cudaGetSymbolAddress((void**)&pv,  g_v);
    cudaGetSymbolAddress((void**)&po,  g_o);
    cudaGetSymbolAddress((void**)&pqh, g_qh);
    cudaGetSymbolAddress((void**)&pkh, g_kh);

    cudaFuncSetAttribute(tf32gemm,
        cudaFuncAttributeMaxDynamicSharedMemorySize, GEMM_SMEM);
    cudaFuncSetAttribute(tf32gemm_qkv,
        cudaFuncAttributeMaxDynamicSharedMemorySize, GEMM_SMEM);
    cudaFuncSetAttribute(flash_attn_mixed,
        cudaFuncAttributeMaxDynamicSharedMemorySize, ATT_SMEM);

    // Fused Q/K/V projections (TF32 tensor cores)
    tf32gemm_qkv<<<dim3(12, NTOK / 128), 256, GEMM_SMEM>>>(
        x, Wq, Wk, Wv, pq, pk, pv);

    // Per-head RMSNorm -> bf16 (qscale folded into Q)
    const float qscale = 0.08838834764831845f;  // 1/sqrt(DH)
    rmsnorm_to_bf16<<<(NTOK * NH  + 7) / 8, 256>>>(pq, qg, pqh, NTOK * NH,  qscale);
    rmsnorm_to_bf16<<<(NTOK * NKV + 7) / 8, 256>>>(pk, kg, pkh, NTOK * NKV, 1.0f);

    // Causal GQA attention (bf16 QK^T + tf32 PV)
    flash_attn_mixed<<<dim3(S_LEN / ATT_BQ, NH, NB), 256, ATT_SMEM>>>(pqh, pkh, pv, po);

    // Output projection + residual (TF32 tensor cores)
    tf32gemm<<<dim3(DMODEL / 256, NTOK / 128), 256, GEMM_SMEM>>>(po, Wo, out, x, DMODEL, DMODEL);
}

// round 14
// speedup vs baseline: 7.1205x; 1.0750x over previous
#include <cuda_runtime.h>
#include <cuda_bf16.h>
#include <cuda_fp16.h>
#include <cstdint>
#include <cstddef>

// Problem constants
#define S_LEN  2048
#define NB     2
#define NH     16
#define NKV    4
#define DH     128
#define DMODEL 2048   // NH*DH
#define KVD    512    // NKV*DH
#define NTOK   (NB*S_LEN)   // 4096

// Scratch (device globals — no allocations allowed)
__device__ float  g_q[(size_t)NTOK * DMODEL];
__device__ float  g_k[(size_t)NTOK * KVD];
__device__ float  g_o[(size_t)NTOK * DMODEL];
__device__ __half g_qh[(size_t)NTOK * DMODEL];  // normalized Q, fp16, qscale folded
__device__ __half g_kh[(size_t)NTOK * KVD];     // normalized K, fp16
__device__ __half g_vh[(size_t)NTOK * KVD];     // V, fp16 (written by QKV GEMM)

#define MMA_TF32(d, a, b)                                               \
    asm volatile(                                                       \
        "mma.sync.aligned.m16n8k8.row.col.f32.tf32.tf32.f32 "           \
        "{%0,%1,%2,%3}, {%4,%5,%6,%7}, {%8,%9}, {%0,%1,%2,%3};\n"       \
        : "+f"(d[0]), "+f"(d[1]), "+f"(d[2]), "+f"(d[3])                \
        : "r"(a[0]), "r"(a[1]), "r"(a[2]), "r"(a[3]),                   \
          "r"(b[0]), "r"(b[1]))

#define MMA_F16(d, a, b)                                                \
    asm volatile(                                                       \
        "mma.sync.aligned.m16n8k16.row.col.f32.f16.f16.f32 "            \
        "{%0,%1,%2,%3}, {%4,%5,%6,%7}, {%8,%9}, {%0,%1,%2,%3};\n"       \
        : "+f"(d[0]), "+f"(d[1]), "+f"(d[2]), "+f"(d[3])                \
        : "r"(a[0]), "r"(a[1]), "r"(a[2]), "r"(a[3]),                   \
          "r"(b[0]), "r"(b[1]))

// ---------------------------------------------------------------------------
// TF32 tensor-core GEMM core (R10 config). Optional fp16 output (V path).
// BM=128, BN=256, BK=32, 256 threads (8 warps), warp tile 64x64 via m16n8k8.
// ---------------------------------------------------------------------------
#define AS_STRIDE 36
#define BS_STRIDE 264
#define ASZ (128 * AS_STRIDE)
#define BSZ (32  * BS_STRIDE)
#define GEMM_SMEM ((2 * (ASZ + BSZ)) * (int)sizeof(float))  // 104448 B

__device__ __forceinline__ void gemm_core(
    const float* __restrict__ A, const float* __restrict__ B,
    float* __restrict__ C, const float* __restrict__ R,
    __half* __restrict__ Ch,   // if non-null: write fp16 here instead of C
    int N, int K, int row0, int col0, float* Asm, float* Bsm)
{
    const int tid  = threadIdx.x;
    const int wid  = tid >> 5;
    const int lane = tid & 31;
    const int wm   = wid >> 2;
    const int wn   = wid & 3;
    const int r    = lane >> 2;
    const int cq   = lane & 3;

    float acc[4][8][4];
#pragma unroll
    for (int mf = 0; mf < 4; mf++)
#pragma unroll
        for (int nf = 0; nf < 8; nf++)
#pragma unroll
            for (int i = 0; i < 4; i++) acc[mf][nf][i] = 0.f;

    auto cp_tile = [&](int kt, int bufi) {
        float* as = Asm + bufi * ASZ;
        float* bs = Bsm + bufi * BSZ;
#pragma unroll
        for (int i = 0; i < 4; i++) {
            int idx = tid + i * 256;
            int ar = idx >> 3, ac = (idx & 7) << 2;
            const float* ga = A + (size_t)(row0 + ar) * K + kt + ac;
            uint32_t sa = (uint32_t)__cvta_generic_to_shared(&as[ar * AS_STRIDE + ac]);
            asm volatile("cp.async.cg.shared.global [%0], [%1], 16;\n"
                         :: "r"(sa), "l"(ga));
        }
#pragma unroll
        for (int i = 0; i < 8; i++) {
            int idx = tid + i * 256;
            int br = idx >> 6, bc = (idx & 63) << 2;
            const float* gb = B + (size_t)(kt + br) * N + col0 + bc;
            uint32_t sb = (uint32_t)__cvta_generic_to_shared(&bs[br * BS_STRIDE + bc]);
            asm volatile("cp.async.cg.shared.global [%0], [%1], 16;\n"
                         :: "r"(sb), "l"(gb));
        }
    };

    const int nk = K / 32;
    cp_tile(0, 0);
    asm volatile("cp.async.commit_group;\n");

    int buf = 0;
    for (int t = 0; t < nk; t++) {
        if (t + 1 < nk) cp_tile((t + 1) * 32, buf ^ 1);
        asm volatile("cp.async.commit_group;\n");
        asm volatile("cp.async.wait_group 1;\n");
        __syncthreads();

        const uint32_t* as = (const uint32_t*)(Asm + buf * ASZ);
        const uint32_t* bs = (const uint32_t*)(Bsm + buf * BSZ);
#pragma unroll
        for (int kk = 0; kk < 32; kk += 8) {
            uint32_t af[4][4], bf[8][2];
#pragma unroll
            for (int mf = 0; mf < 4; mf++) {
                int bm = wm * 64 + mf * 16 + r;
                af[mf][0] = as[(bm    ) * AS_STRIDE + kk + cq    ];
                af[mf][1] = as[(bm + 8) * AS_STRIDE + kk + cq    ];
                af[mf][2] = as[(bm    ) * AS_STRIDE + kk + cq + 4];
                af[mf][3] = as[(bm + 8) * AS_STRIDE + kk + cq + 4];
            }
#pragma unroll
            for (int nf = 0; nf < 8; nf++) {
                int bn = wn * 64 + nf * 8 + r;
                bf[nf][0] = bs[(kk + cq    ) * BS_STRIDE + bn];
                bf[nf][1] = bs[(kk + cq + 4) * BS_STRIDE + bn];
            }
#pragma unroll
            for (int mf = 0; mf < 4; mf++)
#pragma unroll
                for (int nf = 0; nf < 8; nf++)
                    MMA_TF32(acc[mf][nf], af[mf], bf[nf]);
        }
        __syncthreads();
        buf ^= 1;
    }

#pragma unroll
    for (int mf = 0; mf < 4; mf++) {
#pragma unroll
        for (int nf = 0; nf < 8; nf++) {
            int row = row0 + wm * 64 + mf * 16 + r;
            int col = col0 + wn * 64 + nf * 8 + cq * 2;
            float2 v0 = make_float2(acc[mf][nf][0], acc[mf][nf][1]);
            float2 v1 = make_float2(acc[mf][nf][2], acc[mf][nf][3]);
            if (Ch) {
                *(__half2*)&Ch[(size_t)row * N + col]       = __floats2half2_rn(v0.x, v0.y);
                *(__half2*)&Ch[(size_t)(row + 8) * N + col] = __floats2half2_rn(v1.x, v1.y);
            } else {
                if (R) {
                    float2 r0 = *(const float2*)&R[(size_t)row * N + col];
                    float2 r1 = *(const float2*)&R[(size_t)(row + 8) * N + col];
                    v0.x += r0.x; v0.y += r0.y;
                    v1.x += r1.x; v1.y += r1.y;
                }
                *(float2*)&C[(size_t)row * N + col]       = v0;
                *(float2*)&C[(size_t)(row + 8) * N + col] = v1;
            }
        }
    }
}

__global__ __launch_bounds__(256) void tf32gemm(
    const float* __restrict__ A, const float* __restrict__ B,
    float* __restrict__ C, const float* __restrict__ R,
    int N, int K)
{
    extern __shared__ float sm[];
    gemm_core(A, B, C, R, nullptr, N, K, blockIdx.y * 128, blockIdx.x * 256,
              sm, sm + 2 * ASZ);
}

// Fused QKV: bx 0..7 -> Wq (fp32 out), 8..9 -> Wk (fp32 out), 10..11 -> Wv (fp16 out)
__global__ __launch_bounds__(256) void tf32gemm_qkv(
    const float* __restrict__ A,
    const float* __restrict__ Wq, const float* __restrict__ Wk,
    const float* __restrict__ Wv,
    float* __restrict__ Cq, float* __restrict__ Ck, __half* __restrict__ Cvh)
{
    extern __shared__ float sm[];
    const int bx = blockIdx.x;
    if (bx < 8) {
        gemm_core(A, Wq, Cq, nullptr, nullptr, DMODEL, DMODEL,
                  blockIdx.y * 128, bx * 256, sm, sm + 2 * ASZ);
    } else if (bx < 10) {
        gemm_core(A, Wk, Ck, nullptr, nullptr, KVD, DMODEL,
                  blockIdx.y * 128, (bx - 8) * 256, sm, sm + 2 * ASZ);
    } else {
        gemm_core(A, Wv, nullptr, nullptr, Cvh, KVD, DMODEL,
                  blockIdx.y * 128, (bx - 10) * 256, sm, sm + 2 * ASZ);
    }
}

// ---------------------------------------------------------------------------
// Per-head RMSNorm over DH=128 -> fp16 output (scale folded). One warp/row.
// ---------------------------------------------------------------------------
__global__ __launch_bounds__(256) void rmsnorm_to_half(
    const float* __restrict__ t, const float* __restrict__ gamma,
    __half* __restrict__ out, int nrows, float scale)
{
    int row  = blockIdx.x * 8 + (threadIdx.x >> 5);
    if (row >= nrows) return;
    int lane = threadIdx.x & 31;

    float4 v = *(const float4*)&t[(size_t)row * DH + lane * 4];
    float ss = v.x * v.x + v.y * v.y + v.z * v.z + v.w * v.w;
#pragma unroll
    for (int m = 16; m; m >>= 1) ss += __shfl_xor_sync(0xffffffffu, ss, m);
    float r = rsqrtf(ss * (1.0f / DH) + 1e-8f) * scale;

    float4 g = *(const float4*)&gamma[lane * 4];
    __half2 p0 = __floats2half2_rn(v.x * r * g.x, v.y * r * g.y);
    __half2 p1 = __floats2half2_rn(v.z * r * g.z, v.w * r * g.w);
    uint2 packed = make_uint2(*(uint32_t*)&p0, *(uint32_t*)&p1);
    *(uint2*)&out[(size_t)row * DH + lane * 4] = packed;
}

// ---------------------------------------------------------------------------
// All-fp16 causal flash attention (m16n8k16, fp32 accum).
// BQ=128, BK=64, 8 warps, warp = 16 q-rows. V^T via ldmatrix.trans.
// smem words: Kw 64x68 (fp16x2), Vw 64x68 (fp16x2), Pw 128x36 (fp16x2). 53KB.
// ---------------------------------------------------------------------------
#define ATT_BQ 128
#define ATT_BK 64
#define KVW 68     // K/V row stride in 32-bit words (136 halves = 272 B)
#define PSW 36     // P row stride in words (72 halves = 144 B)
#define ATT_SMEM ((64 * KVW + 64 * KVW + 128 * PSW) * (int)sizeof(uint32_t)) // 53248

__global__ __launch_bounds__(256) void flash_attn_f16(
    const __half* __restrict__ Qh, const __half* __restrict__ Kh,
    const __half* __restrict__ Vh, float* __restrict__ O)
{
    extern __shared__ uint32_t smw[];
    uint32_t* Kw = smw;                 // 64*68
    uint32_t* Vw = Kw + 64 * KVW;       // 64*68 (also Q staging, 64-row chunks)
    uint32_t* Pw = Vw + 64 * KVW;       // 128*36

    const int bq  = gridDim.x - 1 - blockIdx.x;   // heavy CTAs first
    const int h   = blockIdx.y;
    const int b   = blockIdx.z;
    const int kvh = h >> 2;

    const int tid  = threadIdx.x;
    const int wid  = tid >> 5;
    const int lane = tid & 31;
    const int r    = lane >> 2;
    const int cq   = lane & 3;
    const int band = wid * 16;

    const __half* Qg = Qh + (size_t)b * S_LEN * DMODEL + h * DH;
    const __half* Kg = Kh + (size_t)b * S_LEN * KVD + kvh * DH;
    const __half* Vg = Vh + (size_t)b * S_LEN * KVD + kvh * DH;
    float*        Og = O  + (size_t)b * S_LEN * DMODEL + h * DH;

    const int q0 = bq * ATT_BQ;

    // Prefetch K tile 0 (fp16: 64 rows x 16 x 16B)
#pragma unroll
    for (int i = tid; i < 1024; i += 256) {
        int rr = i >> 4, ch = i & 15;
        const __half* g = Kg + (size_t)rr * KVD + ch * 8;
        uint32_t s = (uint32_t)__cvta_generic_to_shared(&Kw[rr * KVW + ch * 4]);
        asm volatile("cp.async.cg.shared.global [%0], [%1], 16;\n" :: "r"(s), "l"(g));
    }
    asm volatile("cp.async.commit_group;\n");

    // Stage Q (fp16) through Vw in two 64-row chunks; extract fragments.
    uint32_t qf[8][4];
#pragma unroll
    for (int chunk = 0; chunk < 2; chunk++) {
#pragma unroll
        for (int i = tid; i < 1024; i += 256) {
            int rr = i >> 4, ch = i & 15;
            const __half* g = Qg + (size_t)(q0 + chunk * 64 + rr) * DMODEL + ch * 8;
            uint32_t s = (uint32_t)__cvta_generic_to_shared(&Vw[rr * KVW + ch * 4]);
            asm volatile("cp.async.cg.shared.global [%0], [%1], 16;\n" :: "r"(s), "l"(g));
        }
        asm volatile("cp.async.commit_group;\n");
        asm volatile("cp.async.wait_group 0;\n");
        __syncthreads();
        if ((wid >> 2) == chunk) {
            int lr = (band & 63);
#pragma unroll
            for (int ks = 0; ks < 8; ks++) {
                qf[ks][0] = Vw[(lr + r    ) * KVW + ks * 8 + cq    ];
                qf[ks][1] = Vw[(lr + r + 8) * KVW + ks * 8 + cq    ];
                qf[ks][2] = Vw[(lr + r    ) * KVW + ks * 8 + cq + 4];
                qf[ks][3] = Vw[(lr + r + 8) * KVW + ks * 8 + cq + 4];
            }
        }
        __syncthreads();
    }

    float oacc[16][4];
#pragma unroll
    for (int nf = 0; nf < 16; nf++)
#pragma unroll
        for (int j = 0; j < 4; j++) oacc[nf][j] = 0.f;
    float m0 = -1e30f, m1 = -1e30f, l0 = 0.f, l1 = 0.f;

    // ldmatrix per-lane address components (V^T fragments)
    const int v_klane = lane & 15;             // k row within 16-row block
    const int v_nhalf = (lane >> 4) * 4;       // word offset for n0 / n0+8

    const int ntiles = 2 * bq + 2;
    for (int t = 0; t < ntiles; t++) {
        asm volatile("cp.async.wait_group 0;\n");
        __syncthreads();   // K_t resident; prev PV done with Vw/Pw

        // Prefetch V_t (fp16) — overlaps QK^T
#pragma unroll
        for (int i = tid; i < 1024; i += 256) {
            int rr = i >> 4, ch = i & 15;
            const __half* g = Vg + (size_t)(t * ATT_BK + rr) * KVD + ch * 8;
            uint32_t s = (uint32_t)__cvta_generic_to_shared(&Vw[rr * KVW + ch * 4]);
            asm volatile("cp.async.cg.shared.global [%0], [%1], 16;\n" :: "r"(s), "l"(g));
        }
        asm volatile("cp.async.commit_group;\n");

        // S = Q K^T (fp16 m16n8k16)
        float sacc[8][4];
#pragma unroll
        for (int nf = 0; nf < 8; nf++)
#pragma unroll
            for (int j = 0; j < 4; j++) sacc[nf][j] = 0.f;

#pragma unroll
        for (int ks = 0; ks < 8; ks++) {
#pragma unroll
            for (int nf = 0; nf < 8; nf++) {
                uint32_t bf[2];
                bf[0] = Kw[(nf * 8 + r) * KVW + ks * 8 + cq    ];
                bf[1] = Kw[(nf * 8 + r) * KVW + ks * 8 + cq + 4];
                MMA_F16(sacc[nf], qf[ks], bf);
            }
        }

        // Causal mask (last two tiles only)
        if (t >= 2 * bq) {
            int gq0 = q0 + band + r;
            int gq1 = gq0 + 8;
#pragma unroll
            for (int nf = 0; nf < 8; nf++) {
                int gk = t * ATT_BK + nf * 8 + 2 * cq;
                if (gk     > gq0) sacc[nf][0] = -1e30f;
                if (gk + 1 > gq0) sacc[nf][1] = -1e30f;
                if (gk     > gq1) sacc[nf][2] = -1e30f;
                if (gk + 1 > gq1) sacc[nf][3] = -1e30f;
            }
        }

        // Online softmax (warp-local row reductions over lane bits 0-1)
        float mx0 = -1e30f, mx1 = -1e30f;
#pragma unroll
        for (int nf = 0; nf < 8; nf++) {
            mx0 = fmaxf(mx0, fmaxf(sacc[nf][0], sacc[nf][1]));
            mx1 = fmaxf(mx1, fmaxf(sacc[nf][2], sacc[nf][3]));
        }
        mx0 = fmaxf(mx0, __shfl_xor_sync(0xffffffffu, mx0, 1));
        mx0 = fmaxf(mx0, __shfl_xor_sync(0xffffffffu, mx0, 2));
        mx1 = fmaxf(mx1, __shfl_xor_sync(0xffffffffu, mx1, 1));
        mx1 = fmaxf(mx1, __shfl_xor_sync(0xffffffffu, mx1, 2));

        float mn0 = fmaxf(m0, mx0), mn1 = fmaxf(m1, mx1);
        float sc0 = __expf(m0 - mn0), sc1 = __expf(m1 - mn1);
        m0 = mn0; m1 = mn1;

        float rs0 = 0.f, rs1 = 0.f;
#pragma unroll
        for (int nf = 0; nf < 8; nf++) {
            float p0 = __expf(sacc[nf][0] - mn0);
            float p1 = __expf(sacc[nf][1] - mn0);
            float p2 = __expf(sacc[nf][2] - mn1);
            float p3 = __expf(sacc[nf][3] - mn1);
            rs0 += p0 + p1; rs1 += p2 + p3;
            __half2 h01 = __floats2half2_rn(p0, p1);
            __half2 h23 = __floats2half2_rn(p2, p3);
            Pw[(band + r    ) * PSW + nf * 4 + cq] = *(uint32_t*)&h01;
            Pw[(band + r + 8) * PSW + nf * 4 + cq] = *(uint32_t*)&h23;
        }
        rs0 += __shfl_xor_sync(0xffffffffu, rs0, 1);
        rs0 += __shfl_xor_sync(0xffffffffu, rs0, 2);
        rs1 += __shfl_xor_sync(0xffffffffu, rs1, 1);
        rs1 += __shfl_xor_sync(0xffffffffu, rs1, 2);
        l0 = l0 * sc0 + rs0;
        l1 = l1 * sc1 + rs1;

#pragma unroll
        for (int nf = 0; nf < 16; nf++) {
            oacc[nf][0] *= sc0; oacc[nf][1] *= sc0;
            oacc[nf][2] *= sc1; oacc[nf][3] *= sc1;
        }

        asm volatile("cp.async.wait_group 0;\n");
        __syncthreads();   // V_t resident; all warps past K reads & P stores

        // Prefetch K_{t+1} — overlaps PV
        if (t + 1 < ntiles) {
#pragma unroll
            for (int i = tid; i < 1024; i += 256) {
                int rr = i >> 4, ch = i & 15;
                const __half* g = Kg + (size_t)((t + 1) * ATT_BK + rr) * KVD + ch * 8;
                uint32_t s = (uint32_t)__cvta_generic_to_shared(&Kw[rr * KVW + ch * 4]);
                asm volatile("cp.async.cg.shared.global [%0], [%1], 16;\n" :: "r"(s), "l"(g));
            }
            asm volatile("cp.async.commit_group;\n");
        }

        // O += P V (fp16 m16n8k16, V^T via ldmatrix.trans)
#pragma unroll
        for (int ks = 0; ks < 4; ks++) {
            uint32_t af[4];
            af[0] = Pw[(band + r    ) * PSW + ks * 8 + cq    ];
            af[1] = Pw[(band + r + 8) * PSW + ks * 8 + cq    ];
            af[2] = Pw[(band + r    ) * PSW + ks * 8 + cq + 4];
            af[3] = Pw[(band + r + 8) * PSW + ks * 8 + cq + 4];
            uint32_t vrow = (uint32_t)(ks * 16 + v_klane) * KVW + v_nhalf;
#pragma unroll
            for (int np = 0; np < 8; np++) {
                uint32_t f0, f1, f2, f3;
                uint32_t addr = (uint32_t)__cvta_generic_to_shared(&Vw[vrow + np * 8]);
                asm volatile(
                    "ldmatrix.sync.aligned.m8n8.x4.trans.shared.b16 {%0,%1,%2,%3}, [%4];"
                    : "=r"(f0), "=r"(f1), "=r"(f2), "=r"(f3) : "r"(addr));
                uint32_t b0[2] = {f0, f1};
                uint32_t b1[2] = {f2, f3};
                MMA_F16(oacc[2 * np],     af, b0);
                MMA_F16(oacc[2 * np + 1], af, b1);
            }
        }
    }

    float inv0 = 1.f / l0, inv1 = 1.f / l1;
    size_t row0 = (size_t)(q0 + band + r) * DMODEL;
    size_t row1 = (size_t)(q0 + band + r + 8) * DMODEL;
#pragma unroll
    for (int nf = 0; nf < 16; nf++) {
        int col = nf * 8 + 2 * cq;
        *(float2*)&Og[row0 + col] = make_float2(oacc[nf][0] * inv0, oacc[nf][1] * inv0);
        *(float2*)&Og[row1 + col] = make_float2(oacc[nf][2] * inv1, oacc[nf][3] * inv1);
    }
}

// ---------------------------------------------------------------------------
extern "C" void kernel_launch(void* const* d_in, const int* in_sizes, int n_in,
                              void* d_out, int out_size)
{
    const float* x  = (const float*)d_in[0];
    const float* Wq = (const float*)d_in[1];
    const float* Wk = (const float*)d_in[2];
    const float* Wv = (const float*)d_in[3];
    const float* Wo = (const float*)d_in[4];
    const float* qg = (const float*)d_in[5];
    const float* kg = (const float*)d_in[6];
    float* out = (float*)d_out;

    float *pq, *pk, *po;
    __half *pqh, *pkh, *pvh;
    cudaGetSymbolAddress((void**)&pq,  g_q);
    cudaGetSymbolAddress((void**)&pk,  g_k);
    cudaGetSymbolAddress((void**)&po,  g_o);
    cudaGetSymbolAddress((void**)&pqh, g_qh);
    cudaGetSymbolAddress((void**)&pkh, g_kh);
    cudaGetSymbolAddress((void**)&pvh, g_vh);

    cudaFuncSetAttribute(tf32gemm,
        cudaFuncAttributeMaxDynamicSharedMemorySize, GEMM_SMEM);
    cudaFuncSetAttribute(tf32gemm_qkv,
        cudaFuncAttributeMaxDynamicSharedMemorySize, GEMM_SMEM);
    cudaFuncSetAttribute(flash_attn_f16,
        cudaFuncAttributeMaxDynamicSharedMemorySize, ATT_SMEM);

    // Fused Q/K/V projections (TF32 tensor cores; V written as fp16)
    tf32gemm_qkv<<<dim3(12, NTOK / 128), 256, GEMM_SMEM>>>(
        x, Wq, Wk, Wv, pq, pk, pvh);

    // Per-head RMSNorm -> fp16 (qscale folded into Q)
    const float qscale = 0.08838834764831845f;  // 1/sqrt(DH)
    rmsnorm_to_half<<<(NTOK * NH  + 7) / 8, 256>>>(pq, qg, pqh, NTOK * NH,  qscale);
    rmsnorm_to_half<<<(NTOK * NKV + 7) / 8, 256>>>(pk, kg, pkh, NTOK * NKV, 1.0f);

    // Causal GQA attention (all-fp16 MMA, fp32 accumulate)
    flash_attn_f16<<<dim3(S_LEN / ATT_BQ, NH, NB), 256, ATT_SMEM>>>(pqh, pkh, pvh, po);

    // Output projection + residual (TF32 tensor cores)
    tf32gemm<<<dim3(DMODEL / 256, NTOK / 128), 256, GEMM_SMEM>>>(po, Wo, out, x, DMODEL, DMODEL);
}